// round 13
// baseline (speedup 1.0000x reference)
#include <cuda_runtime.h>
#include <cuda_bf16.h>
#include <math.h>
#include <stdint.h>

#define Bv 2
#define Lv 2048
#define Hv 16
#define DKv 64
#define DMv 1024
#define BHv (Bv*Hv)
#define Mv  (Bv*Lv)    // 4096

// ---------------- scratch (static __device__ globals; no allocation) ----------
__device__ __align__(16) float g_proj[(size_t)Bv*Lv*DMv];
__device__ __align__(16) float g_attn_fb[(size_t)BHv*Lv*Lv];   // fallback if d_out lacks attention
// split-bf16 operand buffers for the dense GEMMs
__device__ __align__(16) __nv_bfloat16 g_Ah[(size_t)Mv*DMv];
__device__ __align__(16) __nv_bfloat16 g_Al[(size_t)Mv*DMv];
__device__ __align__(16) __nv_bfloat16 g_Bh[(size_t)DMv*DMv];
__device__ __align__(16) __nv_bfloat16 g_Bl[(size_t)DMv*DMv];
// split-bf16 Q/K (head-major [bh][L][64]) and transposed V ([bh][64][L])
__device__ __align__(16) __nv_bfloat16 g_Qh[(size_t)BHv*Lv*DKv];
__device__ __align__(16) __nv_bfloat16 g_Ql[(size_t)BHv*Lv*DKv];
__device__ __align__(16) __nv_bfloat16 g_Kh[(size_t)BHv*Lv*DKv];
__device__ __align__(16) __nv_bfloat16 g_Kl[(size_t)BHv*Lv*DKv];
__device__ __align__(16) __nv_bfloat16 g_Vth[(size_t)BHv*DKv*Lv];
__device__ __align__(16) __nv_bfloat16 g_Vtl[(size_t)BHv*DKv*Lv];
__device__ float g_bias_lut[Lv];

// ================= helpers ======================================================
__device__ __forceinline__ uint32_t smem_u32(const void* p) {
    uint32_t a;
    asm("{ .reg .u64 t; cvta.to.shared.u64 t, %1; cvt.u32.u64 %0, t; }" : "=r"(a) : "l"(p));
    return a;
}
__device__ __forceinline__ void cp_async16(uint32_t dst, const void* src) {
    asm volatile("cp.async.cg.shared.global [%0], [%1], 16;\n" :: "r"(dst), "l"(src) : "memory");
}
__device__ __forceinline__ void mma_bf16(float* d, const uint32_t* a, const uint32_t* b) {
    asm volatile(
        "mma.sync.aligned.m16n8k16.row.col.f32.bf16.bf16.f32 "
        "{%0,%1,%2,%3}, {%4,%5,%6,%7}, {%8,%9}, {%0,%1,%2,%3};"
        : "+f"(d[0]), "+f"(d[1]), "+f"(d[2]), "+f"(d[3])
        : "r"(a[0]), "r"(a[1]), "r"(a[2]), "r"(a[3]), "r"(b[0]), "r"(b[1]));
}
#define LDSM_X4(r0,r1,r2,r3,addr) \
    asm volatile("ldmatrix.sync.aligned.m8n8.x4.shared.b16 {%0,%1,%2,%3}, [%4];" \
        : "=r"(r0), "=r"(r1), "=r"(r2), "=r"(r3) : "r"(addr))
#define LDSM_X2(r0,r1,addr) \
    asm volatile("ldmatrix.sync.aligned.m8n8.x2.shared.b16 {%0,%1}, [%2];" \
        : "=r"(r0), "=r"(r1) : "r"(addr))

__device__ __forceinline__ float blk_reduce_sum(float v, float* red) {
#pragma unroll
    for (int o = 16; o > 0; o >>= 1) v += __shfl_xor_sync(0xffffffffu, v, o);
    const int w = threadIdx.x >> 5;
    if ((threadIdx.x & 31) == 0) red[w] = v;
    __syncthreads();
    if (threadIdx.x < 32) {
        float t = (threadIdx.x < 8) ? red[threadIdx.x] : 0.f;
#pragma unroll
        for (int o = 4; o > 0; o >>= 1) t += __shfl_xor_sync(0xffffffffu, t, o);
        if (threadIdx.x == 0) red[0] = t;
    }
    __syncthreads();
    float r = red[0];
    __syncthreads();
    return r;
}

// ---------------- bias LUT -----------------------------------------------------
__global__ void __launch_bounds__(256) bias_lut_kernel(const float* __restrict__ scl_p,
                                                       const float* __restrict__ tau_p) {
    const int i = blockIdx.x * 256 + threadIdx.x;
    if (i < Lv) g_bias_lut[i] = expf(-fabsf((float)i / (*scl_p)) / (*tau_p));
}

// ---------------- fp32 -> (hi, lo) bf16 split ----------------------------------
__global__ void __launch_bounds__(256) split_kernel(const float* __restrict__ src,
                                                    int isB, int n4) {
    const int i = blockIdx.x * 256 + threadIdx.x;
    if (i >= n4) return;
    const float4 v = ((const float4*)src)[i];
    __nv_bfloat16* hi = isB ? g_Bh : g_Ah;
    __nv_bfloat16* lo = isB ? g_Bl : g_Al;
    float x[4] = {v.x, v.y, v.z, v.w};
    unsigned short hs[4], ls[4];
#pragma unroll
    for (int j = 0; j < 4; ++j) {
        __nv_bfloat16 h = __float2bfloat16_rn(x[j]);
        __nv_bfloat16 l = __float2bfloat16_rn(x[j] - __bfloat162float(h));
        hs[j] = __bfloat16_as_ushort(h);
        ls[j] = __bfloat16_as_ushort(l);
    }
    ushort4 hv; hv.x = hs[0]; hv.y = hs[1]; hv.z = hs[2]; hv.w = hs[3];
    ushort4 lv; lv.x = ls[0]; lv.y = ls[1]; lv.z = ls[2]; lv.w = ls[3];
    *(ushort4*)(hi + (size_t)i * 4) = hv;
    *(ushort4*)(lo + (size_t)i * 4) = lv;
}

// ---------------- split-bf16 HMMA NT GEMM (R11 verbatim) ------------------------
#define STR 40
#define TILE_ELE (128*STR)
#define TILEB (TILE_ELE*2)

__global__ void __launch_bounds__(256, 2) tc_gemm(int which)
{
    extern __shared__ __align__(16) __nv_bfloat16 sm[];
    const int tid = threadIdx.x;
    const int wid = tid >> 5;
    const int lane = tid & 31;
    const int bn = blockIdx.x * 128;
    const int bm = blockIdx.y * 128;
    const int wm = (wid >> 2) * 64;
    const int wn = (wid & 3) * 32;

    float acc[4][4][4];
#pragma unroll
    for (int mi = 0; mi < 4; ++mi)
#pragma unroll
        for (int ni = 0; ni < 4; ++ni)
#pragma unroll
            for (int r = 0; r < 4; ++r) acc[mi][ni][r] = 0.f;

    const uint32_t smb = smem_u32(sm);

    auto load_chunk = [&](int c, int stage) {
        const uint32_t sb = smb + (uint32_t)stage * (4u * TILEB);
#pragma unroll
        for (int it = 0; it < 8; ++it) {
            const int sg = tid + it * 256;
            const int t  = sg >> 9;
            const int u  = sg & 511;
            const int row = u >> 2;
            const int c16 = u & 3;
            const char* gb = (t == 0) ? (const char*)g_Ah :
                             (t == 1) ? (const char*)g_Al :
                             (t == 2) ? (const char*)g_Bh : (const char*)g_Bl;
            const int rb = (t < 2) ? bm : bn;
            const char* src = gb + (size_t)(rb + row) * (DMv * 2) + (size_t)c * 64 + c16 * 16;
            const uint32_t dst = sb + (uint32_t)t * TILEB
                               + (uint32_t)(row * STR + c16 * 8) * 2u;
            cp_async16(dst, src);
        }
        asm volatile("cp.async.commit_group;\n" ::: "memory");
    };

    load_chunk(0, 0);

    for (int c = 0; c < 32; ++c) {
        const int buf = c & 1;
        asm volatile("cp.async.wait_group 0;\n" ::: "memory");
        __syncthreads();
        if (c + 1 < 32) load_chunk(c + 1, buf ^ 1);

        const uint32_t sb = smb + (uint32_t)buf * (4u * TILEB);

#pragma unroll
        for (int ks = 0; ks < 2; ++ks) {
            const int kb = ks * 16;
            uint32_t aH[4][4], aL[4][4], bH[4][2], bL[4][2];
            const uint32_t arow = (uint32_t)(((wm + (lane & 15)) * STR + kb + ((lane >> 4) << 3)) * 2);
#pragma unroll
            for (int mi = 0; mi < 4; ++mi) {
                const uint32_t ad = sb + arow + (uint32_t)(mi * 16 * STR * 2);
                LDSM_X4(aH[mi][0], aH[mi][1], aH[mi][2], aH[mi][3], ad);
                LDSM_X4(aL[mi][0], aL[mi][1], aL[mi][2], aL[mi][3], ad + TILEB);
            }
            const uint32_t brow = (uint32_t)((((wn + (lane & 7) + ((lane >> 4) << 3)) * STR)
                                 + kb + (((lane >> 3) & 1) << 3)) * 2);
#pragma unroll
            for (int np = 0; np < 2; ++np) {
                const uint32_t bd = sb + 2u * TILEB + brow + (uint32_t)(np * 16 * STR * 2);
                uint32_t r0, r1, r2, r3;
                LDSM_X4(r0, r1, r2, r3, bd);
                bH[np*2][0] = r0; bH[np*2][1] = r1; bH[np*2+1][0] = r2; bH[np*2+1][1] = r3;
                LDSM_X4(r0, r1, r2, r3, bd + TILEB);
                bL[np*2][0] = r0; bL[np*2][1] = r1; bL[np*2+1][0] = r2; bL[np*2+1][1] = r3;
            }
#pragma unroll
            for (int mi = 0; mi < 4; ++mi)
#pragma unroll
                for (int ni = 0; ni < 4; ++ni) {
                    mma_bf16(acc[mi][ni], aH[mi], bH[ni]);
                    mma_bf16(acc[mi][ni], aH[mi], bL[ni]);
                    mma_bf16(acc[mi][ni], aL[mi], bH[ni]);
                }
        }
        __syncthreads();
    }

    const int r0 = lane >> 2;
    const int cq = (lane & 3) * 2;
#pragma unroll
    for (int mi = 0; mi < 4; ++mi) {
        const int m = bm + wm + mi * 16 + r0;
#pragma unroll
        for (int ni = 0; ni < 4; ++ni) {
            const int n = bn + wn + ni * 8 + cq;
#pragma unroll
            for (int half = 0; half < 2; ++half) {
                const int mm = m + half * 8;
                const float vx = acc[mi][ni][half * 2 + 0];
                const float vy = acc[mi][ni][half * 2 + 1];
                if (which == 3) {
                    float2 val; val.x = vx; val.y = vy;
                    *(float2*)&g_proj[(size_t)mm * DMv + n] = val;
                } else {
                    const int b_ = mm >> 11, l_ = mm & (Lv - 1);
                    const int h_ = n >> 6,  d_ = n & (DKv - 1);
                    const __nv_bfloat16 hx = __float2bfloat16_rn(vx);
                    const __nv_bfloat16 lx = __float2bfloat16_rn(vx - __bfloat162float(hx));
                    const __nv_bfloat16 hy = __float2bfloat16_rn(vy);
                    const __nv_bfloat16 ly = __float2bfloat16_rn(vy - __bfloat162float(hy));
                    if (which == 2) {
                        const size_t basei = ((size_t)(b_ * Hv + h_) * DKv + d_) * Lv + l_;
                        g_Vth[basei] = hx;      g_Vtl[basei] = lx;
                        g_Vth[basei + Lv] = hy; g_Vtl[basei + Lv] = ly;
                    } else {
                        const size_t basei = ((size_t)(b_ * Hv + h_) * Lv + l_) * DKv + d_;
                        __nv_bfloat16* dh = (which == 0) ? g_Qh : g_Kh;
                        __nv_bfloat16* dl = (which == 0) ? g_Ql : g_Kl;
                        ushort2 hv; hv.x = __bfloat16_as_ushort(hx); hv.y = __bfloat16_as_ushort(hy);
                        ushort2 lv; lv.x = __bfloat16_as_ushort(lx); lv.y = __bfloat16_as_ushort(ly);
                        *(ushort2*)&dh[basei] = hv;
                        *(ushort2*)&dl[basei] = lv;
                    }
                }
            }
        }
    }
}

// ---------------- fused attention: scores+softmax+write+P·V (512 threads) ------
// One CTA = 32 query rows of one (b,h). Phases 1-3 are R11-verbatim (S normalized
// in-place). Phase 4: single-group P·V, __syncthreads only, per-warp full-k tiles.
#define SW 1068              // fp32 stride of S rows

__global__ void __launch_bounds__(512) sps_kernel(float* __restrict__ attn_arg,
    const float* __restrict__ mask, const int* __restrict__ ws_p)
{
    extern __shared__ __align__(16) char smz[];
    const int bh = blockIdx.y;
    const int b = bh >> 4, h = bh & 15;
    const int q0 = blockIdx.x << 5;
    const int hs = (*ws_p) >> 1;
    const int tid = threadIdx.x, wid = tid >> 5, lane = tid & 31;
    float* attn = attn_arg ? attn_arg : g_attn_fb;

    float* S = (float*)smz;                          // [32][SW]
    const uint32_t smb = smem_u32(smz);
    const uint32_t offQH = 32u * SW * 4u;            // 136704 (Q hi; later P buffer)
    const uint32_t offQL = offQH + 32*72*2;          // 141312 (Q lo)
    const uint32_t offK0 = offQL + 32*72*2;          // 145920 (K stage0; later V dbl-buf)
    const uint32_t offK1 = offK0 + 2*128*72*2;       // 182784 (K stage1)
    const uint32_t KLH   = 128*72*2;                 // K hi->lo offset within a stage

    __shared__ float s_mx[32], s_inv[32];
    __shared__ int s_masked[32];
    __shared__ int s_any;

    if (tid == 0) s_any = 0;
    if (tid < 32) s_masked[tid] = (mask[b*Lv + q0 + tid] == 0.f);

    int lo = max(0, q0 - hs) & ~7;
    int hi = min(Lv - 1, q0 + 31 + hs);
    int W = hi - lo + 1;
    if (W > SW) { W = SW; hi = lo + SW - 1; }
    const int nch = (W + 127) >> 7;

    // ---- Q tile load (32 rows x 64, hi+lo) ----
    {
        const int arr = tid >> 8, u = tid & 255;
        const int row = u >> 3, c = u & 7;
        const __nv_bfloat16* src = (arr ? g_Ql : g_Qh) + ((size_t)bh*Lv + q0 + row)*DKv + c*8;
        cp_async16(smb + (arr ? offQL : offQH) + (uint32_t)(row*72 + c*8)*2, src);
    }
    // ---- K chunk 0 ----
    {
        const int rows = min(128, hi - lo + 1);
#pragma unroll
        for (int it = 0; it < 4; ++it) {
            const int g = tid + it * 512;
            const int arr = g >> 10, u = g & 1023;
            const int row = u >> 3, c = u & 7;
            if (row < rows) {
                const __nv_bfloat16* src = (arr ? g_Kl : g_Kh) + ((size_t)bh*Lv + lo + row)*DKv + c*8;
                cp_async16(smb + offK0 + (arr ? KLH : 0u) + (uint32_t)(row*72 + c*8)*2, src);
            }
        }
    }
    asm volatile("cp.async.commit_group;\n" ::: "memory");

    // ---- phase 1: banded scores into S (16 warps, warp tile 16x16) ----
    const int wm1 = (wid >> 3) * 16;
    const int wn1 = (wid & 7) * 16;

    asm volatile("cp.async.wait_group 0;\n" ::: "memory");
    __syncthreads();                                  // Q + K0 ready

    uint32_t aHq[4][4], aLq[4][4];                    // hoisted Q fragments
#pragma unroll
    for (int ks = 0; ks < 4; ++ks) {
        const uint32_t arow = (uint32_t)(((wm1 + (lane & 15))*72 + ks*16 + ((lane >> 4) << 3)) * 2);
        LDSM_X4(aHq[ks][0], aHq[ks][1], aHq[ks][2], aHq[ks][3], smb + offQH + arow);
        LDSM_X4(aLq[ks][0], aLq[ks][1], aLq[ks][2], aLq[ks][3], smb + offQL + arow);
    }

    for (int ci = 0; ci < nch; ++ci) {
        if (ci > 0) {
            asm volatile("cp.async.wait_group 0;\n" ::: "memory");
            __syncthreads();
        }
        if (ci + 1 < nch) {
            const int kb2 = lo + (ci+1)*128;
            const int rows = min(128, hi - kb2 + 1);
            const uint32_t sb = ((ci+1) & 1) ? offK1 : offK0;
#pragma unroll
            for (int it = 0; it < 4; ++it) {
                const int g = tid + it * 512;
                const int arr = g >> 10, u = g & 1023;
                const int row = u >> 3, c = u & 7;
                if (row < rows) {
                    const __nv_bfloat16* src = (arr ? g_Kl : g_Kh) + ((size_t)bh*Lv + kb2 + row)*DKv + c*8;
                    cp_async16(smb + sb + (arr ? KLH : 0u) + (uint32_t)(row*72 + c*8)*2, src);
                }
            }
            asm volatile("cp.async.commit_group;\n" ::: "memory");
        }

        const uint32_t kst = (ci & 1) ? offK1 : offK0;
        float acc[2][4];
#pragma unroll
        for (int ni = 0; ni < 2; ++ni)
#pragma unroll
            for (int r = 0; r < 4; ++r) acc[ni][r] = 0.f;

#pragma unroll
        for (int ks = 0; ks < 4; ++ks) {
            const int kb = ks * 16;
            uint32_t bH[2][2], bL[2][2];
            const uint32_t brow = (uint32_t)((((wn1 + (lane & 7) + ((lane >> 4) << 3))*72)
                                 + kb + (((lane >> 3) & 1) << 3)) * 2);
            uint32_t r0, r1, r2, r3;
            LDSM_X4(r0, r1, r2, r3, smb + kst + brow);
            bH[0][0]=r0; bH[0][1]=r1; bH[1][0]=r2; bH[1][1]=r3;
            LDSM_X4(r0, r1, r2, r3, smb + kst + KLH + brow);
            bL[0][0]=r0; bL[0][1]=r1; bL[1][0]=r2; bL[1][1]=r3;
            mma_bf16(acc[0], aHq[ks], bH[0]);
            mma_bf16(acc[1], aHq[ks], bH[1]);
            mma_bf16(acc[0], aHq[ks], bL[0]);
            mma_bf16(acc[1], aHq[ks], bL[1]);
            mma_bf16(acc[0], aLq[ks], bH[0]);
            mma_bf16(acc[1], aLq[ks], bH[1]);
        }

        const int kbase = lo + ci * 128;
#pragma unroll
        for (int ni = 0; ni < 2; ++ni) {
#pragma unroll
            for (int half = 0; half < 2; ++half) {
                const int r = wm1 + (lane >> 2) + half * 8;
                const int q = q0 + r;
                const int cc = wn1 + ni*8 + ((lane & 3) << 1);
                const int k = kbase + cc;
                const int j = k - lo;
                if (j < W)
                    S[r*SW + j] = acc[ni][half*2+0]*0.125f - g_bias_lut[abs(q - k)];
                if (j + 1 < W)
                    S[r*SW + j + 1] = acc[ni][half*2+1]*0.125f - g_bias_lut[abs(q - k - 1)];
            }
        }
    }
    __syncthreads();

    // ---- phase 2: in-smem softmax, normalize S in place (R11 verbatim) --------
    for (int rr = 0; rr < 2; ++rr) {
        const int r = wid * 2 + rr;
        const int q = q0 + r;
        float* Srow = S + r * SW;
        if (!s_masked[r]) {
            const int rlo = max(0, q - hs), rhi = min(Lv - 1, q + hs);
            const int jl = rlo - lo, jh = rhi - lo;
            float mx = -INFINITY;
            for (int j = jl + lane; j <= jh; j += 32) mx = fmaxf(mx, Srow[j]);
#pragma unroll
            for (int o = 16; o > 0; o >>= 1) mx = fmaxf(mx, __shfl_xor_sync(0xffffffffu, mx, o));
            float s = 0.f;
            for (int j = jl + lane; j <= jh; j += 32) { const float e = __expf(Srow[j] - mx); Srow[j] = e; s += e; }
#pragma unroll
            for (int o = 16; o > 0; o >>= 1) s += __shfl_xor_sync(0xffffffffu, s, o);
            const float inv = 1.f / s;
            for (int j = jl + lane; j <= jh; j += 32) Srow[j] *= inv;
        } else {
            if (lane == 0) s_any = 1;
            float mx = -INFINITY;
            for (int c = lane; c < Lv; c += 32) mx = fmaxf(mx, -g_bias_lut[abs(q - c)]);
#pragma unroll
            for (int o = 16; o > 0; o >>= 1) mx = fmaxf(mx, __shfl_xor_sync(0xffffffffu, mx, o));
            float s = 0.f;
            for (int c = lane; c < Lv; c += 32) s += __expf(-g_bias_lut[abs(q - c)] - mx);
#pragma unroll
            for (int o = 16; o > 0; o >>= 1) s += __shfl_xor_sync(0xffffffffu, s, o);
            if (lane == 0) { s_mx[r] = mx; s_inv[r] = 1.f / s; }
        }
    }
    __syncthreads();

    // ---- phase 4 setup: first V prefetch (overlaps phase 3 writes) ------------
    const int nch64 = (W + 63) >> 6;
    auto loadV64 = [&](int ci, int stg) {
        const int kbase = lo + ci * 64;
        const uint32_t sb = offK0 + (uint32_t)stg * 18432u;
#pragma unroll
        for (int it = 0; it < 2; ++it) {
            const int f = tid + it * 512;           // 0..1023
            const int arr = f >> 9;                 // 0 = hi, 1 = lo
            const int u = f & 511;
            const int d = u >> 3, c = u & 7;
            const int kc = kbase + c * 8;
            const uint32_t rel = sb + (arr ? 9216u : 0u) + (uint32_t)(d*72 + c*8)*2u;
            if (kc + 7 < Lv) {
                const __nv_bfloat16* src = (arr ? g_Vtl : g_Vth) + ((size_t)bh*DKv + d)*Lv + kc;
                cp_async16(smb + rel, src);
            } else {
                uint4 z; z.x = 0; z.y = 0; z.z = 0; z.w = 0;
                *(uint4*)(smz + rel) = z;
            }
        }
        asm volatile("cp.async.commit_group;\n" ::: "memory");
    };
    loadV64(0, 0);

    // ---- phase 3: write attention rows (full 2048 wide; R11 verbatim) ---------
    for (int rr = 0; rr < 2; ++rr) {
        const int r = wid * 2 + rr;
        const int q = q0 + r;
        float* rowp = attn + ((size_t)bh * Lv + q) * Lv;
        const float* Srow = S + r * SW;
        if (!s_masked[r]) {
            const int rlo = max(0, q - hs), rhi = min(Lv - 1, q + hs);
            for (int c4 = lane * 4; c4 < Lv; c4 += 128) {
                float4 v;
                v.x = (c4+0 >= rlo && c4+0 <= rhi) ? Srow[c4+0-lo] : 0.f;
                v.y = (c4+1 >= rlo && c4+1 <= rhi) ? Srow[c4+1-lo] : 0.f;
                v.z = (c4+2 >= rlo && c4+2 <= rhi) ? Srow[c4+2-lo] : 0.f;
                v.w = (c4+3 >= rlo && c4+3 <= rhi) ? Srow[c4+3-lo] : 0.f;
                *(float4*)(rowp + c4) = v;
            }
        } else {
            const float mx = s_mx[r], inv = s_inv[r];
            for (int c4 = lane * 4; c4 < Lv; c4 += 128) {
                float4 v;
                v.x = __expf(-g_bias_lut[abs(q - (c4+0))] - mx) * inv;
                v.y = __expf(-g_bias_lut[abs(q - (c4+1))] - mx) * inv;
                v.z = __expf(-g_bias_lut[abs(q - (c4+2))] - mx) * inv;
                v.w = __expf(-g_bias_lut[abs(q - (c4+3))] - mx) * inv;
                *(float4*)(rowp + c4) = v;
            }
        }
    }

    // ---- phase 4: P·V, single group, __syncthreads only ------------------------
    // P buffer at offQH (dead Q): [32][72] bf16. V double-buffer at offK0 (dead K):
    // stage = [64 d][72] hi (9216 B) + lo (9216 B). Warp tile: 16 q x 8 d, full k.
    auto convP = [&](int ci) {
        const int kbase = lo + ci * 64;
        const int row = tid >> 4;           // 0..31
        const int cb  = (tid & 15) * 4;     // 0..60
        const int q = q0 + row;
        const bool mrow = (s_masked[row] != 0);
        const int rlo = max(0, q - hs), rhi = min(Lv - 1, q + hs);
        const float* Srow = S + row * SW;
#pragma unroll
        for (int cc = 0; cc < 4; cc += 2) {
            const int kk = kbase + cb + cc;
            float p0 = 0.f, p1 = 0.f;
            if (!mrow) {
                if (kk >= rlo && kk <= rhi)       p0 = Srow[kk - lo];
                if (kk+1 >= rlo && kk+1 <= rhi)   p1 = Srow[kk+1 - lo];
            }
            const uint32_t pk = ((uint32_t)__bfloat16_as_ushort(__float2bfloat16_rn(p1)) << 16)
                              |  (uint32_t)__bfloat16_as_ushort(__float2bfloat16_rn(p0));
            *(uint32_t*)(smz + offQH + (size_t)(row*72 + cb + cc)*2) = pk;
        }
    };

    const int wm5 = (wid >> 3) * 16;        // 0 / 16
    const int wn5 = (wid & 7) * 8;          // 0..56
    float oacc[4];
    oacc[0] = 0.f; oacc[1] = 0.f; oacc[2] = 0.f; oacc[3] = 0.f;

    int st = 0;
    for (int ci = 0; ci < nch64; ++ci) {
        asm volatile("cp.async.wait_group 0;\n" ::: "memory");
        __syncthreads();                    // V(st) ready; previous MMA complete
        if (ci + 1 < nch64) loadV64(ci + 1, st ^ 1);
        convP(ci);
        __syncthreads();                    // P ready

        const uint32_t vst = offK0 + (uint32_t)st * 18432u;
#pragma unroll
        for (int ks = 0; ks < 4; ++ks) {
            const int kb = ks * 16;
            uint32_t aP[4], vH[2], vL[2];
            const uint32_t arow = (uint32_t)(((wm5 + (lane & 15))*72 + kb + ((lane >> 4) << 3)) * 2);
            LDSM_X4(aP[0], aP[1], aP[2], aP[3], smb + offQH + arow);
            const uint32_t brow = (uint32_t)((((wn5 + (lane & 7))*72)
                                 + kb + (((lane >> 3) & 1) << 3)) * 2);
            LDSM_X2(vH[0], vH[1], smb + vst + brow);
            LDSM_X2(vL[0], vL[1], smb + vst + 9216u + brow);
            mma_bf16(oacc, aP, vH);
            mma_bf16(oacc, aP, vL);
        }
        st ^= 1;
    }

    // ---- epilogue: write split-bf16 ctx into g_Ah/g_Al -------------------------
#pragma unroll
    for (int half = 0; half < 2; ++half) {
        const int r = wm5 + (lane >> 2) + half * 8;
        if (s_masked[r]) continue;                    // slow path owns masked rows
        const int q = q0 + r;
        const int d = wn5 + ((lane & 3) << 1);
        const float vx = oacc[half*2+0];
        const float vy = oacc[half*2+1];
        const __nv_bfloat16 hx = __float2bfloat16_rn(vx);
        const __nv_bfloat16 lx = __float2bfloat16_rn(vx - __bfloat162float(hx));
        const __nv_bfloat16 hy = __float2bfloat16_rn(vy);
        const __nv_bfloat16 ly = __float2bfloat16_rn(vy - __bfloat162float(hy));
        ushort2 hv; hv.x = __bfloat16_as_ushort(hx); hv.y = __bfloat16_as_ushort(hy);
        ushort2 lv; lv.x = __bfloat16_as_ushort(lx); lv.y = __bfloat16_as_ushort(ly);
        const size_t rowbase = ((size_t)b * Lv + q) * DMv + h * DKv;
        *(ushort2*)&g_Ah[rowbase + d] = hv;
        *(ushort2*)&g_Al[rowbase + d] = lv;
    }

    // ---- masked-row slow path (full-row P·V) -----------------------------------
    if (s_any) {
        for (int r = wid; r < 32; r += 16) {
            if (!s_masked[r]) continue;
            const int q = q0 + r;
            const float mx = s_mx[r], inv = s_inv[r];
            const __nv_bfloat16* vhp = g_Vth + (size_t)bh * DKv * Lv;
            const __nv_bfloat16* vlp = g_Vtl + (size_t)bh * DKv * Lv;
            float a0 = 0.f, a1 = 0.f;
            for (int kk = 0; kk < Lv; ++kk) {
                const float p = __expf(-g_bias_lut[abs(q - kk)] - mx) * inv;
                a0 += p * (__bfloat162float(vhp[(size_t)lane*Lv + kk]) + __bfloat162float(vlp[(size_t)lane*Lv + kk]));
                a1 += p * (__bfloat162float(vhp[(size_t)(lane+32)*Lv + kk]) + __bfloat162float(vlp[(size_t)(lane+32)*Lv + kk]));
            }
            const size_t rowbase = ((size_t)b * Lv + q) * DMv + h * DKv;
#pragma unroll
            for (int u = 0; u < 2; ++u) {
                const float vv = u ? a1 : a0;
                const int d = lane + u * 32;
                const __nv_bfloat16 hx = __float2bfloat16_rn(vv);
                const __nv_bfloat16 lx = __float2bfloat16_rn(vv - __bfloat162float(hx));
                g_Ah[rowbase + d] = hx;
                g_Al[rowbase + d] = lx;
            }
        }
    }
}

// ---------------- residual + LayerNorm -----------------------------------------
__global__ void __launch_bounds__(256) ln_kernel(const float* __restrict__ qin,
    const float* __restrict__ lnw, const float* __restrict__ lnb,
    float* __restrict__ out)
{
    const int m = blockIdx.x;
    const int tid = threadIdx.x;
    __shared__ float xs[DMv];
    __shared__ float red[32];

    float s = 0.f;
    for (int i = tid; i < DMv; i += 256) {
        const float v = g_proj[(size_t)m * DMv + i] + qin[(size_t)m * DMv + i];
        xs[i] = v; s += v;
    }
    s = blk_reduce_sum(s, red);
    const float mean = s * (1.f / DMv);

    float vs = 0.f;
    for (int i = tid; i < DMv; i += 256) { const float d = xs[i] - mean; vs += d * d; }
    vs = blk_reduce_sum(vs, red);
    const float inv = rsqrtf(vs * (1.f / DMv) + 1e-6f);

    for (int i = tid; i < DMv; i += 256)
        out[(size_t)m * DMv + i] = (xs[i] - mean) * inv * lnw[i] + lnb[i];
}

// ---------------- launcher ------------------------------------------------------
extern "C" void kernel_launch(void* const* d_in, const int* in_sizes, int n_in,
                              void* d_out, int out_size)
{
    const float* q    = (const float*)d_in[0];
    const float* k    = (const float*)d_in[1];
    const float* v    = (const float*)d_in[2];
    const float* mask = (const float*)d_in[3];
    const float* Wq   = (const float*)d_in[4];
    const float* Wk   = (const float*)d_in[5];
    const float* Wv   = (const float*)d_in[6];
    const float* Wo   = (const float*)d_in[7];
    const float* scl  = (const float*)d_in[8];
    const float* tau  = (const float*)d_in[9];
    const float* lnw  = (const float*)d_in[10];
    const float* lnb  = (const float*)d_in[11];
    const int*   ws   = (const int*)d_in[12];
    (void)in_sizes; (void)n_in;

    const int gemm_smem = 2 * 4 * TILEB;                        // 81920 B
    const int sps_smem  = 32*SW*4 + 2*32*72*2 + 2*2*128*72*2;   // 219648 B
    cudaFuncSetAttribute(tc_gemm, cudaFuncAttributeMaxDynamicSharedMemorySize, gemm_smem);
    cudaFuncSetAttribute(sps_kernel, cudaFuncAttributeMaxDynamicSharedMemorySize, sps_smem);

    float* xout = (float*)d_out;
    const long long XN = (long long)Bv * Lv * DMv;
    const long long AN = (long long)BHv * Lv * Lv;
    float* attn_out = ((long long)out_size >= XN + AN) ? (xout + XN) : nullptr;

    const int A4 = Mv * DMv / 4;
    const int B4 = DMv * DMv / 4;
    const dim3 gg(DMv / 128, Mv / 128);   // (8, 32)

    bias_lut_kernel<<<8, 256>>>(scl, tau);

    split_kernel<<<A4 / 256, 256>>>(q,  0, A4);
    split_kernel<<<B4 / 256, 256>>>(Wq, 1, B4);
    tc_gemm<<<gg, 256, gemm_smem>>>(0);

    split_kernel<<<A4 / 256, 256>>>(k,  0, A4);
    split_kernel<<<B4 / 256, 256>>>(Wk, 1, B4);
    tc_gemm<<<gg, 256, gemm_smem>>>(1);

    split_kernel<<<A4 / 256, 256>>>(v,  0, A4);
    split_kernel<<<B4 / 256, 256>>>(Wv, 1, B4);
    tc_gemm<<<gg, 256, gemm_smem>>>(2);

    // fused: scores + softmax + attention write + P·V (writes split ctx directly)
    sps_kernel<<<dim3(Lv/32, BHv), 512, sps_smem>>>(attn_out, mask, ws);

    split_kernel<<<B4 / 256, 256>>>(Wo, 1, B4);
    tc_gemm<<<gg, 256, gemm_smem>>>(3);

    ln_kernel<<<Mv, 256>>>(q, lnw, lnb, xout);
}

// round 14
// speedup vs baseline: 1.0831x; 1.0831x over previous
#include <cuda_runtime.h>
#include <cuda_bf16.h>
#include <math.h>
#include <stdint.h>

#define Bv 2
#define Lv 2048
#define Hv 16
#define DKv 64
#define DMv 1024
#define BHv (Bv*Hv)
#define Mv  (Bv*Lv)    // 4096

#define ASZ ((size_t)Mv*DMv)
#define BSZ ((size_t)DMv*DMv)

// ---------------- scratch (static __device__ globals; no allocation) ----------
__device__ __align__(16) float g_proj[(size_t)Bv*Lv*DMv];
__device__ __align__(16) float g_attn_fb[(size_t)BHv*Lv*Lv];   // fallback if d_out lacks attention
// split-bf16 operand buffers (3 slots: QKV merged splits; slot 0 reused for Wo)
__device__ __align__(16) __nv_bfloat16 g_Ah[3*ASZ];
__device__ __align__(16) __nv_bfloat16 g_Al[3*ASZ];
__device__ __align__(16) __nv_bfloat16 g_Bh[3*BSZ];
__device__ __align__(16) __nv_bfloat16 g_Bl[3*BSZ];
// split-bf16 Q/K (head-major [bh][L][64]) and transposed V ([bh][64][L])
__device__ __align__(16) __nv_bfloat16 g_Qh[(size_t)BHv*Lv*DKv];
__device__ __align__(16) __nv_bfloat16 g_Ql[(size_t)BHv*Lv*DKv];
__device__ __align__(16) __nv_bfloat16 g_Kh[(size_t)BHv*Lv*DKv];
__device__ __align__(16) __nv_bfloat16 g_Kl[(size_t)BHv*Lv*DKv];
__device__ __align__(16) __nv_bfloat16 g_Vth[(size_t)BHv*DKv*Lv];
__device__ __align__(16) __nv_bfloat16 g_Vtl[(size_t)BHv*DKv*Lv];
__device__ float g_bias_lut[Lv];

// ================= helpers ======================================================
__device__ __forceinline__ uint32_t smem_u32(const void* p) {
    uint32_t a;
    asm("{ .reg .u64 t; cvta.to.shared.u64 t, %1; cvt.u32.u64 %0, t; }" : "=r"(a) : "l"(p));
    return a;
}
__device__ __forceinline__ void cp_async16(uint32_t dst, const void* src) {
    asm volatile("cp.async.cg.shared.global [%0], [%1], 16;\n" :: "r"(dst), "l"(src) : "memory");
}
__device__ __forceinline__ void mma_bf16(float* d, const uint32_t* a, const uint32_t* b) {
    asm volatile(
        "mma.sync.aligned.m16n8k16.row.col.f32.bf16.bf16.f32 "
        "{%0,%1,%2,%3}, {%4,%5,%6,%7}, {%8,%9}, {%0,%1,%2,%3};"
        : "+f"(d[0]), "+f"(d[1]), "+f"(d[2]), "+f"(d[3])
        : "r"(a[0]), "r"(a[1]), "r"(a[2]), "r"(a[3]), "r"(b[0]), "r"(b[1]));
}
#define LDSM_X4(r0,r1,r2,r3,addr) \
    asm volatile("ldmatrix.sync.aligned.m8n8.x4.shared.b16 {%0,%1,%2,%3}, [%4];" \
        : "=r"(r0), "=r"(r1), "=r"(r2), "=r"(r3) : "r"(addr))

__device__ __forceinline__ float blk_reduce_sum(float v, float* red) {
#pragma unroll
    for (int o = 16; o > 0; o >>= 1) v += __shfl_xor_sync(0xffffffffu, v, o);
    const int w = threadIdx.x >> 5;
    if ((threadIdx.x & 31) == 0) red[w] = v;
    __syncthreads();
    if (threadIdx.x < 32) {
        float t = (threadIdx.x < 8) ? red[threadIdx.x] : 0.f;
#pragma unroll
        for (int o = 4; o > 0; o >>= 1) t += __shfl_xor_sync(0xffffffffu, t, o);
        if (threadIdx.x == 0) red[0] = t;
    }
    __syncthreads();
    float r = red[0];
    __syncthreads();
    return r;
}

// ---------------- bias LUT -----------------------------------------------------
__global__ void __launch_bounds__(256) bias_lut_kernel(const float* __restrict__ scl_p,
                                                       const float* __restrict__ tau_p) {
    const int i = blockIdx.x * 256 + threadIdx.x;
    if (i < Lv) g_bias_lut[i] = expf(-fabsf((float)i / (*scl_p)) / (*tau_p));
}

// ---------------- fp32 -> (hi, lo) bf16 splits ----------------------------------
__device__ __forceinline__ void split4(const float4 v, ushort4& hv, ushort4& lv) {
    float x[4] = {v.x, v.y, v.z, v.w};
    unsigned short hs[4], ls[4];
#pragma unroll
    for (int j = 0; j < 4; ++j) {
        __nv_bfloat16 h = __float2bfloat16_rn(x[j]);
        __nv_bfloat16 l = __float2bfloat16_rn(x[j] - __bfloat162float(h));
        hs[j] = __bfloat16_as_ushort(h);
        ls[j] = __bfloat16_as_ushort(l);
    }
    hv.x=hs[0]; hv.y=hs[1]; hv.z=hs[2]; hv.w=hs[3];
    lv.x=ls[0]; lv.y=ls[1]; lv.z=ls[2]; lv.w=ls[3];
}
__global__ void __launch_bounds__(256) splitA3_kernel(const float* __restrict__ a0,
    const float* __restrict__ a1, const float* __restrict__ a2) {
    const int z = blockIdx.z;
    const int i = blockIdx.x * 256 + threadIdx.x;        // < ASZ/4
    const float* src = (z == 0) ? a0 : (z == 1) ? a1 : a2;
    const float4 v = ((const float4*)src)[i];
    ushort4 hv, lv; split4(v, hv, lv);
    *(ushort4*)(g_Ah + (size_t)z*ASZ + (size_t)i*4) = hv;
    *(ushort4*)(g_Al + (size_t)z*ASZ + (size_t)i*4) = lv;
}
__global__ void __launch_bounds__(256) splitB3_kernel(const float* __restrict__ b0,
    const float* __restrict__ b1, const float* __restrict__ b2) {
    const int z = blockIdx.z;
    const int i = blockIdx.x * 256 + threadIdx.x;        // < BSZ/4
    const float* src = (z == 0) ? b0 : (z == 1) ? b1 : b2;
    const float4 v = ((const float4*)src)[i];
    ushort4 hv, lv; split4(v, hv, lv);
    *(ushort4*)(g_Bh + (size_t)z*BSZ + (size_t)i*4) = hv;
    *(ushort4*)(g_Bl + (size_t)z*BSZ + (size_t)i*4) = lv;
}
__global__ void __launch_bounds__(256) splitB1_kernel(const float* __restrict__ src) {
    const int i = blockIdx.x * 256 + threadIdx.x;        // < BSZ/4
    const float4 v = ((const float4*)src)[i];
    ushort4 hv, lv; split4(v, hv, lv);
    *(ushort4*)(g_Bh + (size_t)i*4) = hv;
    *(ushort4*)(g_Bl + (size_t)i*4) = lv;
}

// ---------------- split-bf16 HMMA NT GEMM (R11 core, slot-indexed) --------------
#define STR 40
#define TILE_ELE (128*STR)
#define TILEB (TILE_ELE*2)

__global__ void __launch_bounds__(256, 2) tc_gemm(int which)
{
    extern __shared__ __align__(16) __nv_bfloat16 sm[];
    const int slot = (which < 3) ? which : 0;
    const int tid = threadIdx.x;
    const int wid = tid >> 5;
    const int lane = tid & 31;
    const int bn = blockIdx.x * 128;
    const int bm = blockIdx.y * 128;
    const int wm = (wid >> 2) * 64;
    const int wn = (wid & 3) * 32;

    const __nv_bfloat16* Ahp = g_Ah + (size_t)slot*ASZ;
    const __nv_bfloat16* Alp = g_Al + (size_t)slot*ASZ;
    const __nv_bfloat16* Bhp = g_Bh + (size_t)slot*BSZ;
    const __nv_bfloat16* Blp = g_Bl + (size_t)slot*BSZ;

    float acc[4][4][4];
#pragma unroll
    for (int mi = 0; mi < 4; ++mi)
#pragma unroll
        for (int ni = 0; ni < 4; ++ni)
#pragma unroll
            for (int r = 0; r < 4; ++r) acc[mi][ni][r] = 0.f;

    const uint32_t smb = smem_u32(sm);

    auto load_chunk = [&](int c, int stage) {
        const uint32_t sb = smb + (uint32_t)stage * (4u * TILEB);
#pragma unroll
        for (int it = 0; it < 8; ++it) {
            const int sg = tid + it * 256;
            const int t  = sg >> 9;
            const int u  = sg & 511;
            const int row = u >> 2;
            const int c16 = u & 3;
            const char* gb = (t == 0) ? (const char*)Ahp :
                             (t == 1) ? (const char*)Alp :
                             (t == 2) ? (const char*)Bhp : (const char*)Blp;
            const int rb = (t < 2) ? bm : bn;
            const char* src = gb + (size_t)(rb + row) * (DMv * 2) + (size_t)c * 64 + c16 * 16;
            const uint32_t dst = sb + (uint32_t)t * TILEB
                               + (uint32_t)(row * STR + c16 * 8) * 2u;
            cp_async16(dst, src);
        }
        asm volatile("cp.async.commit_group;\n" ::: "memory");
    };

    load_chunk(0, 0);

    for (int c = 0; c < 32; ++c) {
        const int buf = c & 1;
        asm volatile("cp.async.wait_group 0;\n" ::: "memory");
        __syncthreads();
        if (c + 1 < 32) load_chunk(c + 1, buf ^ 1);

        const uint32_t sb = smb + (uint32_t)buf * (4u * TILEB);

#pragma unroll
        for (int ks = 0; ks < 2; ++ks) {
            const int kb = ks * 16;
            uint32_t aH[4][4], aL[4][4], bH[4][2], bL[4][2];
            const uint32_t arow = (uint32_t)(((wm + (lane & 15)) * STR + kb + ((lane >> 4) << 3)) * 2);
#pragma unroll
            for (int mi = 0; mi < 4; ++mi) {
                const uint32_t ad = sb + arow + (uint32_t)(mi * 16 * STR * 2);
                LDSM_X4(aH[mi][0], aH[mi][1], aH[mi][2], aH[mi][3], ad);
                LDSM_X4(aL[mi][0], aL[mi][1], aL[mi][2], aL[mi][3], ad + TILEB);
            }
            const uint32_t brow = (uint32_t)((((wn + (lane & 7) + ((lane >> 4) << 3)) * STR)
                                 + kb + (((lane >> 3) & 1) << 3)) * 2);
#pragma unroll
            for (int np = 0; np < 2; ++np) {
                const uint32_t bd = sb + 2u * TILEB + brow + (uint32_t)(np * 16 * STR * 2);
                uint32_t r0, r1, r2, r3;
                LDSM_X4(r0, r1, r2, r3, bd);
                bH[np*2][0] = r0; bH[np*2][1] = r1; bH[np*2+1][0] = r2; bH[np*2+1][1] = r3;
                LDSM_X4(r0, r1, r2, r3, bd + TILEB);
                bL[np*2][0] = r0; bL[np*2][1] = r1; bL[np*2+1][0] = r2; bL[np*2+1][1] = r3;
            }
#pragma unroll
            for (int mi = 0; mi < 4; ++mi)
#pragma unroll
                for (int ni = 0; ni < 4; ++ni) {
                    mma_bf16(acc[mi][ni], aH[mi], bH[ni]);
                    mma_bf16(acc[mi][ni], aH[mi], bL[ni]);
                    mma_bf16(acc[mi][ni], aL[mi], bH[ni]);
                }
        }
        __syncthreads();
    }

    const int r0 = lane >> 2;
    const int cq = (lane & 3) * 2;
#pragma unroll
    for (int mi = 0; mi < 4; ++mi) {
        const int m = bm + wm + mi * 16 + r0;
#pragma unroll
        for (int ni = 0; ni < 4; ++ni) {
            const int n = bn + wn + ni * 8 + cq;
#pragma unroll
            for (int half = 0; half < 2; ++half) {
                const int mm = m + half * 8;
                const float vx = acc[mi][ni][half * 2 + 0];
                const float vy = acc[mi][ni][half * 2 + 1];
                if (which == 3) {
                    float2 val; val.x = vx; val.y = vy;
                    *(float2*)&g_proj[(size_t)mm * DMv + n] = val;
                } else {
                    const int b_ = mm >> 11, l_ = mm & (Lv - 1);
                    const int h_ = n >> 6,  d_ = n & (DKv - 1);
                    const __nv_bfloat16 hx = __float2bfloat16_rn(vx);
                    const __nv_bfloat16 lx = __float2bfloat16_rn(vx - __bfloat162float(hx));
                    const __nv_bfloat16 hy = __float2bfloat16_rn(vy);
                    const __nv_bfloat16 ly = __float2bfloat16_rn(vy - __bfloat162float(hy));
                    if (which == 2) {
                        const size_t basei = ((size_t)(b_ * Hv + h_) * DKv + d_) * Lv + l_;
                        g_Vth[basei] = hx;      g_Vtl[basei] = lx;
                        g_Vth[basei + Lv] = hy; g_Vtl[basei + Lv] = ly;
                    } else {
                        const size_t basei = ((size_t)(b_ * Hv + h_) * Lv + l_) * DKv + d_;
                        __nv_bfloat16* dh = (which == 0) ? g_Qh : g_Kh;
                        __nv_bfloat16* dl = (which == 0) ? g_Ql : g_Kl;
                        ushort2 hv; hv.x = __bfloat16_as_ushort(hx); hv.y = __bfloat16_as_ushort(hy);
                        ushort2 lv; lv.x = __bfloat16_as_ushort(lx); lv.y = __bfloat16_as_ushort(ly);
                        *(ushort2*)&dh[basei] = hv;
                        *(ushort2*)&dl[basei] = lv;
                    }
                }
            }
        }
    }
}

// ---------------- fused scores + softmax + attention write (R11 verbatim) ------
#define SW 1068              // fp32 stride of S rows

__global__ void __launch_bounds__(512) sps_kernel(float* __restrict__ attn_arg,
    const float* __restrict__ mask, const int* __restrict__ ws_p)
{
    extern __shared__ __align__(16) char smz[];
    const int bh = blockIdx.y;
    const int b = bh >> 4;
    const int q0 = blockIdx.x << 5;
    const int hs = (*ws_p) >> 1;
    const int tid = threadIdx.x, wid = tid >> 5, lane = tid & 31;
    float* attn = attn_arg ? attn_arg : g_attn_fb;

    float* S = (float*)smz;                          // [32][SW]
    const uint32_t smb = smem_u32(smz);
    const uint32_t offQH = 32u * SW * 4u;            // 136704
    const uint32_t offQL = offQH + 32*72*2;
    const uint32_t offK0 = offQL + 32*72*2;          // 145920
    const uint32_t offK1 = offK0 + 2*128*72*2;       // 182784
    const uint32_t KLH   = 128*72*2;                 // hi->lo offset within a stage

    __shared__ float s_mx[32], s_inv[32];
    __shared__ int s_masked[32];

    if (tid < 32) s_masked[tid] = (mask[b*Lv + q0 + tid] == 0.f);

    int lo = max(0, q0 - hs) & ~7;
    int hi = min(Lv - 1, q0 + 31 + hs);
    int W = hi - lo + 1;
    if (W > SW) { W = SW; hi = lo + SW - 1; }
    const int nch = (W + 127) >> 7;

    // ---- Q tile load (32 rows x 64, hi+lo) ----
    {
        const int arr = tid >> 8, u = tid & 255;
        const int row = u >> 3, c = u & 7;
        const __nv_bfloat16* src = (arr ? g_Ql : g_Qh) + ((size_t)bh*Lv + q0 + row)*DKv + c*8;
        cp_async16(smb + (arr ? offQL : offQH) + (uint32_t)(row*72 + c*8)*2, src);
    }
    // ---- K chunk 0 ----
    {
        const int rows = min(128, hi - lo + 1);
#pragma unroll
        for (int it = 0; it < 4; ++it) {
            const int g = tid + it * 512;
            const int arr = g >> 10, u = g & 1023;
            const int row = u >> 3, c = u & 7;
            if (row < rows) {
                const __nv_bfloat16* src = (arr ? g_Kl : g_Kh) + ((size_t)bh*Lv + lo + row)*DKv + c*8;
                cp_async16(smb + offK0 + (arr ? KLH : 0u) + (uint32_t)(row*72 + c*8)*2, src);
            }
        }
    }
    asm volatile("cp.async.commit_group;\n" ::: "memory");

    const int wm1 = (wid >> 3) * 16;
    const int wn1 = (wid & 7) * 16;

    asm volatile("cp.async.wait_group 0;\n" ::: "memory");
    __syncthreads();                                  // Q + K0 ready

    uint32_t aHq[4][4], aLq[4][4];                    // hoisted Q fragments
#pragma unroll
    for (int ks = 0; ks < 4; ++ks) {
        const uint32_t arow = (uint32_t)(((wm1 + (lane & 15))*72 + ks*16 + ((lane >> 4) << 3)) * 2);
        LDSM_X4(aHq[ks][0], aHq[ks][1], aHq[ks][2], aHq[ks][3], smb + offQH + arow);
        LDSM_X4(aLq[ks][0], aLq[ks][1], aLq[ks][2], aLq[ks][3], smb + offQL + arow);
    }

    for (int ci = 0; ci < nch; ++ci) {
        if (ci > 0) {
            asm volatile("cp.async.wait_group 0;\n" ::: "memory");
            __syncthreads();
        }
        if (ci + 1 < nch) {
            const int kb2 = lo + (ci+1)*128;
            const int rows = min(128, hi - kb2 + 1);
            const uint32_t sb = ((ci+1) & 1) ? offK1 : offK0;
#pragma unroll
            for (int it = 0; it < 4; ++it) {
                const int g = tid + it * 512;
                const int arr = g >> 10, u = g & 1023;
                const int row = u >> 3, c = u & 7;
                if (row < rows) {
                    const __nv_bfloat16* src = (arr ? g_Kl : g_Kh) + ((size_t)bh*Lv + kb2 + row)*DKv + c*8;
                    cp_async16(smb + sb + (arr ? KLH : 0u) + (uint32_t)(row*72 + c*8)*2, src);
                }
            }
            asm volatile("cp.async.commit_group;\n" ::: "memory");
        }

        const uint32_t kst = (ci & 1) ? offK1 : offK0;
        float acc[2][4];
#pragma unroll
        for (int ni = 0; ni < 2; ++ni)
#pragma unroll
            for (int r = 0; r < 4; ++r) acc[ni][r] = 0.f;

#pragma unroll
        for (int ks = 0; ks < 4; ++ks) {
            const int kb = ks * 16;
            uint32_t bH[2][2], bL[2][2];
            const uint32_t brow = (uint32_t)((((wn1 + (lane & 7) + ((lane >> 4) << 3))*72)
                                 + kb + (((lane >> 3) & 1) << 3)) * 2);
            uint32_t r0, r1, r2, r3;
            LDSM_X4(r0, r1, r2, r3, smb + kst + brow);
            bH[0][0]=r0; bH[0][1]=r1; bH[1][0]=r2; bH[1][1]=r3;
            LDSM_X4(r0, r1, r2, r3, smb + kst + KLH + brow);
            bL[0][0]=r0; bL[0][1]=r1; bL[1][0]=r2; bL[1][1]=r3;
            mma_bf16(acc[0], aHq[ks], bH[0]);
            mma_bf16(acc[1], aHq[ks], bH[1]);
            mma_bf16(acc[0], aHq[ks], bL[0]);
            mma_bf16(acc[1], aHq[ks], bL[1]);
            mma_bf16(acc[0], aLq[ks], bH[0]);
            mma_bf16(acc[1], aLq[ks], bH[1]);
        }

        const int kbase = lo + ci * 128;
#pragma unroll
        for (int ni = 0; ni < 2; ++ni) {
#pragma unroll
            for (int half = 0; half < 2; ++half) {
                const int r = wm1 + (lane >> 2) + half * 8;
                const int q = q0 + r;
                const int cc = wn1 + ni*8 + ((lane & 3) << 1);
                const int k = kbase + cc;
                const int j = k - lo;
                if (j < W)
                    S[r*SW + j] = acc[ni][half*2+0]*0.125f - g_bias_lut[abs(q - k)];
                if (j + 1 < W)
                    S[r*SW + j + 1] = acc[ni][half*2+1]*0.125f - g_bias_lut[abs(q - k - 1)];
            }
        }
    }
    __syncthreads();

    // ---- softmax (normalize S in place) ----
    for (int rr = 0; rr < 2; ++rr) {
        const int r = wid * 2 + rr;
        const int q = q0 + r;
        float* Srow = S + r * SW;
        if (!s_masked[r]) {
            const int rlo = max(0, q - hs), rhi = min(Lv - 1, q + hs);
            const int jl = rlo - lo, jh = rhi - lo;
            float mx = -INFINITY;
            for (int j = jl + lane; j <= jh; j += 32) mx = fmaxf(mx, Srow[j]);
#pragma unroll
            for (int o = 16; o > 0; o >>= 1) mx = fmaxf(mx, __shfl_xor_sync(0xffffffffu, mx, o));
            float s = 0.f;
            for (int j = jl + lane; j <= jh; j += 32) { const float e = __expf(Srow[j] - mx); Srow[j] = e; s += e; }
#pragma unroll
            for (int o = 16; o > 0; o >>= 1) s += __shfl_xor_sync(0xffffffffu, s, o);
            const float inv = 1.f / s;
            for (int j = jl + lane; j <= jh; j += 32) Srow[j] *= inv;
        } else {
            float mx = -INFINITY;
            for (int c = lane; c < Lv; c += 32) mx = fmaxf(mx, -g_bias_lut[abs(q - c)]);
#pragma unroll
            for (int o = 16; o > 0; o >>= 1) mx = fmaxf(mx, __shfl_xor_sync(0xffffffffu, mx, o));
            float s = 0.f;
            for (int c = lane; c < Lv; c += 32) s += __expf(-g_bias_lut[abs(q - c)] - mx);
#pragma unroll
            for (int o = 16; o > 0; o >>= 1) s += __shfl_xor_sync(0xffffffffu, s, o);
            if (lane == 0) { s_mx[r] = mx; s_inv[r] = 1.f / s; }
        }
    }
    __syncthreads();

    // ---- write attention rows (full 2048 wide) ----
    for (int rr = 0; rr < 2; ++rr) {
        const int r = wid * 2 + rr;
        const int q = q0 + r;
        float* rowp = attn + ((size_t)bh * Lv + q) * Lv;
        const float* Srow = S + r * SW;
        if (!s_masked[r]) {
            const int rlo = max(0, q - hs), rhi = min(Lv - 1, q + hs);
            for (int c4 = lane * 4; c4 < Lv; c4 += 128) {
                float4 v;
                v.x = (c4+0 >= rlo && c4+0 <= rhi) ? Srow[c4+0-lo] : 0.f;
                v.y = (c4+1 >= rlo && c4+1 <= rhi) ? Srow[c4+1-lo] : 0.f;
                v.z = (c4+2 >= rlo && c4+2 <= rhi) ? Srow[c4+2-lo] : 0.f;
                v.w = (c4+3 >= rlo && c4+3 <= rhi) ? Srow[c4+3-lo] : 0.f;
                *(float4*)(rowp + c4) = v;
            }
        } else {
            const float mx = s_mx[r], inv = s_inv[r];
            for (int c4 = lane * 4; c4 < Lv; c4 += 128) {
                float4 v;
                v.x = __expf(-g_bias_lut[abs(q - (c4+0))] - mx) * inv;
                v.y = __expf(-g_bias_lut[abs(q - (c4+1))] - mx) * inv;
                v.z = __expf(-g_bias_lut[abs(q - (c4+2))] - mx) * inv;
                v.w = __expf(-g_bias_lut[abs(q - (c4+3))] - mx) * inv;
                *(float4*)(rowp + c4) = v;
            }
        }
    }
}

// ---------------- ctx = attn @ V via HMMA; V double-buffered prefetch ----------
#define TS 72
__global__ void __launch_bounds__(256) av2_kernel(const float* __restrict__ attn_arg,
    const float* __restrict__ mask, const int* __restrict__ ws_p)
{
    const int q0 = blockIdx.x << 7;
    const int bh = blockIdx.y;
    const int b = bh >> 4, h = bh & 15;
    const int hs = (*ws_p) >> 1;
    const int tid = threadIdx.x, wid = tid >> 5, lane = tid & 31;

    const float* attn = attn_arg ? attn_arg : g_attn_fb;

    extern __shared__ __align__(16) __nv_bfloat16 smy[];   // P[128*TS] + 2 V stages
    const uint32_t smb = smem_u32(smy);
    const uint32_t PB = 128 * TS * 2;     // 18432: P buffer
    const uint32_t VST = 2 * 64 * TS * 2; // 18432: one V stage (hi 9216 + lo 9216)

    __shared__ int s_all;
    if (tid == 0) s_all = 1;
    __syncthreads();
    if (tid < 128 && mask[b * Lv + q0 + tid] == 0.f) s_all = 0;
    __syncthreads();
    const int allm = s_all;

    const int wm = (wid >> 1) * 32, wn = (wid & 1) * 32;
    float acc[2][4][4];
#pragma unroll
    for (int mi = 0; mi < 2; ++mi)
#pragma unroll
        for (int ni = 0; ni < 4; ++ni)
#pragma unroll
            for (int r = 0; r < 4; ++r) acc[mi][ni][r] = 0.f;

    const float* abase = attn + (size_t)bh * Lv * Lv;
    const __nv_bfloat16* vh = g_Vth + (size_t)bh * DKv * Lv;
    const __nv_bfloat16* vl = g_Vtl + (size_t)bh * DKv * Lv;

    // contiguous active chunk range (equivalent to the old skip-scan)
    int mstart, mlast;
    if (allm) {
        const int a = q0 - hs;
        mstart = (a > 0) ? ((a >> 6) << 6) : 0;
        int e = q0 + 127 + hs; if (e > Lv - 1) e = Lv - 1;
        mlast = (e >> 6) << 6;
    } else {
        mstart = 0; mlast = Lv - 64;
    }
    const int nchv = ((mlast - mstart) >> 6) + 1;

    auto loadV = [&](int m0, int st) {
        const uint32_t sb = smb + PB + (uint32_t)st * VST;
#pragma unroll
        for (int it = 0; it < 4; ++it) {
            const int f = tid + it * 256;
            const int arr = f >> 9;
            const int u = f & 511;
            const int row = u >> 3, c = u & 7;
            const __nv_bfloat16* src = (arr ? vl : vh) + (size_t)row * Lv + m0 + c * 8;
            const uint32_t dst = sb + (arr ? 9216u : 0u) + (uint32_t)(row * TS + c * 8) * 2u;
            cp_async16(dst, src);
        }
        asm volatile("cp.async.commit_group;\n" ::: "memory");
    };

    loadV(mstart, 0);

    for (int ci = 0; ci < nchv; ++ci) {
        const int m0 = mstart + ci * 64;
        const int st = ci & 1;
        asm volatile("cp.async.wait_group 0;\n" ::: "memory");
        __syncthreads();                 // V(st) ready; previous MMA done (P overwrite safe)

        if (ci + 1 < nchv) loadV(m0 + 64, st ^ 1);   // overlap with conv + MMA

        // P fp32 -> bf16 smem
#pragma unroll
        for (int it = 0; it < 8; ++it) {
            const int f = tid + it * 256;
            const int row = f >> 4, c4 = (f & 15) << 2;
            const float4 a = *(const float4*)(abase + (size_t)(q0 + row) * Lv + m0 + c4);
            const uint32_t p0 = ((uint32_t)__bfloat16_as_ushort(__float2bfloat16_rn(a.y)) << 16)
                              |  (uint32_t)__bfloat16_as_ushort(__float2bfloat16_rn(a.x));
            const uint32_t p1 = ((uint32_t)__bfloat16_as_ushort(__float2bfloat16_rn(a.w)) << 16)
                              |  (uint32_t)__bfloat16_as_ushort(__float2bfloat16_rn(a.z));
            uint2 pv; pv.x = p0; pv.y = p1;
            *(uint2*)((char*)smy + (size_t)(row * TS + c4) * 2) = pv;
        }
        __syncthreads();                 // P visible

        const uint32_t vbase = smb + PB + (uint32_t)st * VST;
#pragma unroll
        for (int ks = 0; ks < 4; ++ks) {
            const int kb = ks * 16;
            uint32_t aP[2][4], bVh[4][2], bVl[4][2];
            const uint32_t arow = (uint32_t)(((wm + (lane & 15)) * TS + kb + ((lane >> 4) << 3)) * 2);
#pragma unroll
            for (int mi = 0; mi < 2; ++mi) {
                const uint32_t ad = smb + arow + (uint32_t)(mi * 16 * TS * 2);
                LDSM_X4(aP[mi][0], aP[mi][1], aP[mi][2], aP[mi][3], ad);
            }
            const uint32_t brow = (uint32_t)((((wn + (lane & 7) + ((lane >> 4) << 3)) * TS)
                                 + kb + (((lane >> 3) & 1) << 3)) * 2);
#pragma unroll
            for (int np = 0; np < 2; ++np) {
                const uint32_t bd = vbase + brow + (uint32_t)(np * 16 * TS * 2);
                uint32_t r0, r1, r2, r3;
                LDSM_X4(r0, r1, r2, r3, bd);
                bVh[np*2][0] = r0; bVh[np*2][1] = r1; bVh[np*2+1][0] = r2; bVh[np*2+1][1] = r3;
                LDSM_X4(r0, r1, r2, r3, bd + 9216u);
                bVl[np*2][0] = r0; bVl[np*2][1] = r1; bVl[np*2+1][0] = r2; bVl[np*2+1][1] = r3;
            }
#pragma unroll
            for (int mi = 0; mi < 2; ++mi)
#pragma unroll
                for (int ni = 0; ni < 4; ++ni) {
                    mma_bf16(acc[mi][ni], aP[mi], bVh[ni]);
                    mma_bf16(acc[mi][ni], aP[mi], bVl[ni]);
                }
        }
    }

    // epilogue: write hi/lo bf16 split directly into g_Ah/g_Al (slot 0 = A of Wo GEMM)
#pragma unroll
    for (int mi = 0; mi < 2; ++mi) {
#pragma unroll
        for (int half = 0; half < 2; ++half) {
            const int q = q0 + wm + mi * 16 + (lane >> 2) + half * 8;
            const size_t rowbase = ((size_t)b * Lv + q) * DMv + h * DKv;
#pragma unroll
            for (int ni = 0; ni < 4; ++ni) {
                const int d = wn + ni * 8 + ((lane & 3) << 1);
                const float vx = acc[mi][ni][half*2+0];
                const float vy = acc[mi][ni][half*2+1];
                const __nv_bfloat16 hx = __float2bfloat16_rn(vx);
                const __nv_bfloat16 lx = __float2bfloat16_rn(vx - __bfloat162float(hx));
                const __nv_bfloat16 hy = __float2bfloat16_rn(vy);
                const __nv_bfloat16 ly = __float2bfloat16_rn(vy - __bfloat162float(hy));
                ushort2 hv; hv.x = __bfloat16_as_ushort(hx); hv.y = __bfloat16_as_ushort(hy);
                ushort2 lv; lv.x = __bfloat16_as_ushort(lx); lv.y = __bfloat16_as_ushort(ly);
                *(ushort2*)&g_Ah[rowbase + d] = hv;
                *(ushort2*)&g_Al[rowbase + d] = lv;
            }
        }
    }
}

// ---------------- residual + LayerNorm -----------------------------------------
__global__ void __launch_bounds__(256) ln_kernel(const float* __restrict__ qin,
    const float* __restrict__ lnw, const float* __restrict__ lnb,
    float* __restrict__ out)
{
    const int m = blockIdx.x;
    const int tid = threadIdx.x;
    __shared__ float xs[DMv];
    __shared__ float red[32];

    float s = 0.f;
    for (int i = tid; i < DMv; i += 256) {
        const float v = g_proj[(size_t)m * DMv + i] + qin[(size_t)m * DMv + i];
        xs[i] = v; s += v;
    }
    s = blk_reduce_sum(s, red);
    const float mean = s * (1.f / DMv);

    float vs = 0.f;
    for (int i = tid; i < DMv; i += 256) { const float d = xs[i] - mean; vs += d * d; }
    vs = blk_reduce_sum(vs, red);
    const float inv = rsqrtf(vs * (1.f / DMv) + 1e-6f);

    for (int i = tid; i < DMv; i += 256)
        out[(size_t)m * DMv + i] = (xs[i] - mean) * inv * lnw[i] + lnb[i];
}

// ---------------- launcher ------------------------------------------------------
extern "C" void kernel_launch(void* const* d_in, const int* in_sizes, int n_in,
                              void* d_out, int out_size)
{
    const float* q    = (const float*)d_in[0];
    const float* k    = (const float*)d_in[1];
    const float* v    = (const float*)d_in[2];
    const float* mask = (const float*)d_in[3];
    const float* Wq   = (const float*)d_in[4];
    const float* Wk   = (const float*)d_in[5];
    const float* Wv   = (const float*)d_in[6];
    const float* Wo   = (const float*)d_in[7];
    const float* scl  = (const float*)d_in[8];
    const float* tau  = (const float*)d_in[9];
    const float* lnw  = (const float*)d_in[10];
    const float* lnb  = (const float*)d_in[11];
    const int*   ws   = (const int*)d_in[12];
    (void)in_sizes; (void)n_in;

    const int gemm_smem = 2 * 4 * TILEB;                        // 81920 B
    const int sps_smem  = 32*SW*4 + 2*32*72*2 + 2*2*128*72*2;   // 219648 B
    const int av_smem   = 128*TS*2 + 2*2*64*TS*2;               // 55296 B
    cudaFuncSetAttribute(tc_gemm, cudaFuncAttributeMaxDynamicSharedMemorySize, gemm_smem);
    cudaFuncSetAttribute(sps_kernel, cudaFuncAttributeMaxDynamicSharedMemorySize, sps_smem);
    cudaFuncSetAttribute(av2_kernel, cudaFuncAttributeMaxDynamicSharedMemorySize, av_smem);

    float* xout = (float*)d_out;
    const long long XN = (long long)Bv * Lv * DMv;
    const long long AN = (long long)BHv * Lv * Lv;
    float* attn_out = ((long long)out_size >= XN + AN) ? (xout + XN) : nullptr;

    const int A4 = Mv * DMv / 4;
    const int B4 = DMv * DMv / 4;
    const dim3 gg(DMv / 128, Mv / 128);   // (8, 32)

    bias_lut_kernel<<<8, 256>>>(scl, tau);

    splitA3_kernel<<<dim3(A4/256, 1, 3), 256>>>(q, k, v);
    splitB3_kernel<<<dim3(B4/256, 1, 3), 256>>>(Wq, Wk, Wv);
    tc_gemm<<<gg, 256, gemm_smem>>>(0);
    tc_gemm<<<gg, 256, gemm_smem>>>(1);
    tc_gemm<<<gg, 256, gemm_smem>>>(2);

    sps_kernel<<<dim3(Lv/32, BHv), 512, sps_smem>>>(attn_out, mask, ws);
    av2_kernel<<<dim3(Lv/128, BHv), 256, av_smem>>>(attn_out, mask, ws);   // writes split A (slot 0)

    splitB1_kernel<<<B4/256, 256>>>(Wo);
    tc_gemm<<<gg, 256, gemm_smem>>>(3);

    ln_kernel<<<Mv, 256>>>(q, lnw, lnb, xout);
}

// round 15
// speedup vs baseline: 1.1143x; 1.0289x over previous
#include <cuda_runtime.h>
#include <cuda_bf16.h>
#include <math.h>
#include <stdint.h>

#define Bv 2
#define Lv 2048
#define Hv 16
#define DKv 64
#define DMv 1024
#define BHv (Bv*Hv)
#define Mv  (Bv*Lv)    // 4096

#define ASZ ((size_t)Mv*DMv)
#define BSZ ((size_t)DMv*DMv)
#define PBW 1152       // bf16 band stride for g_Pb

// ---------------- scratch (static __device__ globals; no allocation) ----------
__device__ __align__(16) float g_proj[(size_t)Bv*Lv*DMv];
__device__ __align__(16) float g_attn_fb[(size_t)BHv*Lv*Lv];   // fallback if d_out lacks attention
// split-bf16 operand buffers (3 slots: QKV merged splits; slot 0 reused for Wo)
__device__ __align__(16) __nv_bfloat16 g_Ah[3*ASZ];
__device__ __align__(16) __nv_bfloat16 g_Al[3*ASZ];
__device__ __align__(16) __nv_bfloat16 g_Bh[3*BSZ];
__device__ __align__(16) __nv_bfloat16 g_Bl[3*BSZ];
// split-bf16 Q/K (head-major [bh][L][64]) and transposed V ([bh][64][L])
__device__ __align__(16) __nv_bfloat16 g_Qh[(size_t)BHv*Lv*DKv];
__device__ __align__(16) __nv_bfloat16 g_Ql[(size_t)BHv*Lv*DKv];
__device__ __align__(16) __nv_bfloat16 g_Kh[(size_t)BHv*Lv*DKv];
__device__ __align__(16) __nv_bfloat16 g_Kl[(size_t)BHv*Lv*DKv];
__device__ __align__(16) __nv_bfloat16 g_Vth[(size_t)BHv*DKv*Lv];
__device__ __align__(16) __nv_bfloat16 g_Vtl[(size_t)BHv*DKv*Lv];
// compact bf16 P band written by sps, consumed by av2 fast path
__device__ __align__(16) __nv_bfloat16 g_Pb[(size_t)BHv*Lv*PBW];
__device__ float g_bias_lut[Lv];

// ================= helpers ======================================================
__device__ __forceinline__ uint32_t smem_u32(const void* p) {
    uint32_t a;
    asm("{ .reg .u64 t; cvta.to.shared.u64 t, %1; cvt.u32.u64 %0, t; }" : "=r"(a) : "l"(p));
    return a;
}
__device__ __forceinline__ void cp_async16(uint32_t dst, const void* src) {
    asm volatile("cp.async.cg.shared.global [%0], [%1], 16;\n" :: "r"(dst), "l"(src) : "memory");
}
__device__ __forceinline__ void mma_bf16(float* d, const uint32_t* a, const uint32_t* b) {
    asm volatile(
        "mma.sync.aligned.m16n8k16.row.col.f32.bf16.bf16.f32 "
        "{%0,%1,%2,%3}, {%4,%5,%6,%7}, {%8,%9}, {%0,%1,%2,%3};"
        : "+f"(d[0]), "+f"(d[1]), "+f"(d[2]), "+f"(d[3])
        : "r"(a[0]), "r"(a[1]), "r"(a[2]), "r"(a[3]), "r"(b[0]), "r"(b[1]));
}
#define LDSM_X4(r0,r1,r2,r3,addr) \
    asm volatile("ldmatrix.sync.aligned.m8n8.x4.shared.b16 {%0,%1,%2,%3}, [%4];" \
        : "=r"(r0), "=r"(r1), "=r"(r2), "=r"(r3) : "r"(addr))

__device__ __forceinline__ float blk_reduce_sum(float v, float* red) {
#pragma unroll
    for (int o = 16; o > 0; o >>= 1) v += __shfl_xor_sync(0xffffffffu, v, o);
    const int w = threadIdx.x >> 5;
    if ((threadIdx.x & 31) == 0) red[w] = v;
    __syncthreads();
    if (threadIdx.x < 32) {
        float t = (threadIdx.x < 8) ? red[threadIdx.x] : 0.f;
#pragma unroll
        for (int o = 4; o > 0; o >>= 1) t += __shfl_xor_sync(0xffffffffu, t, o);
        if (threadIdx.x == 0) red[0] = t;
    }
    __syncthreads();
    float r = red[0];
    __syncthreads();
    return r;
}

// ---------------- bias LUT -----------------------------------------------------
__global__ void __launch_bounds__(256) bias_lut_kernel(const float* __restrict__ scl_p,
                                                       const float* __restrict__ tau_p) {
    const int i = blockIdx.x * 256 + threadIdx.x;
    if (i < Lv) g_bias_lut[i] = expf(-fabsf((float)i / (*scl_p)) / (*tau_p));
}

// ---------------- fp32 -> (hi, lo) bf16 splits ----------------------------------
__device__ __forceinline__ void split4(const float4 v, ushort4& hv, ushort4& lv) {
    float x[4] = {v.x, v.y, v.z, v.w};
    unsigned short hs[4], ls[4];
#pragma unroll
    for (int j = 0; j < 4; ++j) {
        __nv_bfloat16 h = __float2bfloat16_rn(x[j]);
        __nv_bfloat16 l = __float2bfloat16_rn(x[j] - __bfloat162float(h));
        hs[j] = __bfloat16_as_ushort(h);
        ls[j] = __bfloat16_as_ushort(l);
    }
    hv.x=hs[0]; hv.y=hs[1]; hv.z=hs[2]; hv.w=hs[3];
    lv.x=ls[0]; lv.y=ls[1]; lv.z=ls[2]; lv.w=ls[3];
}
__global__ void __launch_bounds__(256) splitA3_kernel(const float* __restrict__ a0,
    const float* __restrict__ a1, const float* __restrict__ a2) {
    const int z = blockIdx.z;
    const int i = blockIdx.x * 256 + threadIdx.x;
    const float* src = (z == 0) ? a0 : (z == 1) ? a1 : a2;
    const float4 v = ((const float4*)src)[i];
    ushort4 hv, lv; split4(v, hv, lv);
    *(ushort4*)(g_Ah + (size_t)z*ASZ + (size_t)i*4) = hv;
    *(ushort4*)(g_Al + (size_t)z*ASZ + (size_t)i*4) = lv;
}
__global__ void __launch_bounds__(256) splitB3_kernel(const float* __restrict__ b0,
    const float* __restrict__ b1, const float* __restrict__ b2) {
    const int z = blockIdx.z;
    const int i = blockIdx.x * 256 + threadIdx.x;
    const float* src = (z == 0) ? b0 : (z == 1) ? b1 : b2;
    const float4 v = ((const float4*)src)[i];
    ushort4 hv, lv; split4(v, hv, lv);
    *(ushort4*)(g_Bh + (size_t)z*BSZ + (size_t)i*4) = hv;
    *(ushort4*)(g_Bl + (size_t)z*BSZ + (size_t)i*4) = lv;
}
__global__ void __launch_bounds__(256) splitB1_kernel(const float* __restrict__ src) {
    const int i = blockIdx.x * 256 + threadIdx.x;
    const float4 v = ((const float4*)src)[i];
    ushort4 hv, lv; split4(v, hv, lv);
    *(ushort4*)(g_Bh + (size_t)i*4) = hv;
    *(ushort4*)(g_Bl + (size_t)i*4) = lv;
}

// ---------------- split-bf16 HMMA NT GEMM (R14 verbatim) ------------------------
#define STR 40
#define TILE_ELE (128*STR)
#define TILEB (TILE_ELE*2)

__global__ void __launch_bounds__(256, 2) tc_gemm(int which)
{
    extern __shared__ __align__(16) __nv_bfloat16 sm[];
    const int slot = (which < 3) ? which : 0;
    const int tid = threadIdx.x;
    const int wid = tid >> 5;
    const int lane = tid & 31;
    const int bn = blockIdx.x * 128;
    const int bm = blockIdx.y * 128;
    const int wm = (wid >> 2) * 64;
    const int wn = (wid & 3) * 32;

    const __nv_bfloat16* Ahp = g_Ah + (size_t)slot*ASZ;
    const __nv_bfloat16* Alp = g_Al + (size_t)slot*ASZ;
    const __nv_bfloat16* Bhp = g_Bh + (size_t)slot*BSZ;
    const __nv_bfloat16* Blp = g_Bl + (size_t)slot*BSZ;

    float acc[4][4][4];
#pragma unroll
    for (int mi = 0; mi < 4; ++mi)
#pragma unroll
        for (int ni = 0; ni < 4; ++ni)
#pragma unroll
            for (int r = 0; r < 4; ++r) acc[mi][ni][r] = 0.f;

    const uint32_t smb = smem_u32(sm);

    auto load_chunk = [&](int c, int stage) {
        const uint32_t sb = smb + (uint32_t)stage * (4u * TILEB);
#pragma unroll
        for (int it = 0; it < 8; ++it) {
            const int sg = tid + it * 256;
            const int t  = sg >> 9;
            const int u  = sg & 511;
            const int row = u >> 2;
            const int c16 = u & 3;
            const char* gb = (t == 0) ? (const char*)Ahp :
                             (t == 1) ? (const char*)Alp :
                             (t == 2) ? (const char*)Bhp : (const char*)Blp;
            const int rb = (t < 2) ? bm : bn;
            const char* src = gb + (size_t)(rb + row) * (DMv * 2) + (size_t)c * 64 + c16 * 16;
            const uint32_t dst = sb + (uint32_t)t * TILEB
                               + (uint32_t)(row * STR + c16 * 8) * 2u;
            cp_async16(dst, src);
        }
        asm volatile("cp.async.commit_group;\n" ::: "memory");
    };

    load_chunk(0, 0);

    for (int c = 0; c < 32; ++c) {
        const int buf = c & 1;
        asm volatile("cp.async.wait_group 0;\n" ::: "memory");
        __syncthreads();
        if (c + 1 < 32) load_chunk(c + 1, buf ^ 1);

        const uint32_t sb = smb + (uint32_t)buf * (4u * TILEB);

#pragma unroll
        for (int ks = 0; ks < 2; ++ks) {
            const int kb = ks * 16;
            uint32_t aH[4][4], aL[4][4], bH[4][2], bL[4][2];
            const uint32_t arow = (uint32_t)(((wm + (lane & 15)) * STR + kb + ((lane >> 4) << 3)) * 2);
#pragma unroll
            for (int mi = 0; mi < 4; ++mi) {
                const uint32_t ad = sb + arow + (uint32_t)(mi * 16 * STR * 2);
                LDSM_X4(aH[mi][0], aH[mi][1], aH[mi][2], aH[mi][3], ad);
                LDSM_X4(aL[mi][0], aL[mi][1], aL[mi][2], aL[mi][3], ad + TILEB);
            }
            const uint32_t brow = (uint32_t)((((wn + (lane & 7) + ((lane >> 4) << 3)) * STR)
                                 + kb + (((lane >> 3) & 1) << 3)) * 2);
#pragma unroll
            for (int np = 0; np < 2; ++np) {
                const uint32_t bd = sb + 2u * TILEB + brow + (uint32_t)(np * 16 * STR * 2);
                uint32_t r0, r1, r2, r3;
                LDSM_X4(r0, r1, r2, r3, bd);
                bH[np*2][0] = r0; bH[np*2][1] = r1; bH[np*2+1][0] = r2; bH[np*2+1][1] = r3;
                LDSM_X4(r0, r1, r2, r3, bd + TILEB);
                bL[np*2][0] = r0; bL[np*2][1] = r1; bL[np*2+1][0] = r2; bL[np*2+1][1] = r3;
            }
#pragma unroll
            for (int mi = 0; mi < 4; ++mi)
#pragma unroll
                for (int ni = 0; ni < 4; ++ni) {
                    mma_bf16(acc[mi][ni], aH[mi], bH[ni]);
                    mma_bf16(acc[mi][ni], aH[mi], bL[ni]);
                    mma_bf16(acc[mi][ni], aL[mi], bH[ni]);
                }
        }
        __syncthreads();
    }

    const int r0 = lane >> 2;
    const int cq = (lane & 3) * 2;
#pragma unroll
    for (int mi = 0; mi < 4; ++mi) {
        const int m = bm + wm + mi * 16 + r0;
#pragma unroll
        for (int ni = 0; ni < 4; ++ni) {
            const int n = bn + wn + ni * 8 + cq;
#pragma unroll
            for (int half = 0; half < 2; ++half) {
                const int mm = m + half * 8;
                const float vx = acc[mi][ni][half * 2 + 0];
                const float vy = acc[mi][ni][half * 2 + 1];
                if (which == 3) {
                    float2 val; val.x = vx; val.y = vy;
                    *(float2*)&g_proj[(size_t)mm * DMv + n] = val;
                } else {
                    const int b_ = mm >> 11, l_ = mm & (Lv - 1);
                    const int h_ = n >> 6,  d_ = n & (DKv - 1);
                    const __nv_bfloat16 hx = __float2bfloat16_rn(vx);
                    const __nv_bfloat16 lx = __float2bfloat16_rn(vx - __bfloat162float(hx));
                    const __nv_bfloat16 hy = __float2bfloat16_rn(vy);
                    const __nv_bfloat16 ly = __float2bfloat16_rn(vy - __bfloat162float(hy));
                    if (which == 2) {
                        const size_t basei = ((size_t)(b_ * Hv + h_) * DKv + d_) * Lv + l_;
                        g_Vth[basei] = hx;      g_Vtl[basei] = lx;
                        g_Vth[basei + Lv] = hy; g_Vtl[basei + Lv] = ly;
                    } else {
                        const size_t basei = ((size_t)(b_ * Hv + h_) * Lv + l_) * DKv + d_;
                        __nv_bfloat16* dh = (which == 0) ? g_Qh : g_Kh;
                        __nv_bfloat16* dl = (which == 0) ? g_Ql : g_Kl;
                        ushort2 hv; hv.x = __bfloat16_as_ushort(hx); hv.y = __bfloat16_as_ushort(hy);
                        ushort2 lv; lv.x = __bfloat16_as_ushort(lx); lv.y = __bfloat16_as_ushort(ly);
                        *(ushort2*)&dh[basei] = hv;
                        *(ushort2*)&dl[basei] = lv;
                    }
                }
            }
        }
    }
}

// ---------------- fused scores + softmax + attention + bf16 band write ---------
#define SW 1068              // fp32 stride of S rows

__global__ void __launch_bounds__(512) sps_kernel(float* __restrict__ attn_arg,
    const float* __restrict__ mask, const int* __restrict__ ws_p)
{
    extern __shared__ __align__(16) char smz[];
    const int bh = blockIdx.y;
    const int b = bh >> 4;
    const int q0 = blockIdx.x << 5;
    const int hs = (*ws_p) >> 1;
    const int tid = threadIdx.x, wid = tid >> 5, lane = tid & 31;
    float* attn = attn_arg ? attn_arg : g_attn_fb;

    float* S = (float*)smz;                          // [32][SW]
    const uint32_t smb = smem_u32(smz);
    const uint32_t offQH = 32u * SW * 4u;            // 136704
    const uint32_t offQL = offQH + 32*72*2;
    const uint32_t offK0 = offQL + 32*72*2;          // 145920
    const uint32_t offK1 = offK0 + 2*128*72*2;       // 182784
    const uint32_t KLH   = 128*72*2;                 // hi->lo offset within a stage

    __shared__ float s_mx[32], s_inv[32];
    __shared__ int s_masked[32];

    if (tid < 32) s_masked[tid] = (mask[b*Lv + q0 + tid] == 0.f);

    int lo = max(0, q0 - hs) & ~7;
    int hi = min(Lv - 1, q0 + 31 + hs);
    int W = hi - lo + 1;
    if (W > SW) { W = SW; hi = lo + SW - 1; }
    const int nch = (W + 127) >> 7;

    // ---- Q tile load (32 rows x 64, hi+lo) ----
    {
        const int arr = tid >> 8, u = tid & 255;
        const int row = u >> 3, c = u & 7;
        const __nv_bfloat16* src = (arr ? g_Ql : g_Qh) + ((size_t)bh*Lv + q0 + row)*DKv + c*8;
        cp_async16(smb + (arr ? offQL : offQH) + (uint32_t)(row*72 + c*8)*2, src);
    }
    // ---- K chunk 0 ----
    {
        const int rows = min(128, hi - lo + 1);
#pragma unroll
        for (int it = 0; it < 4; ++it) {
            const int g = tid + it * 512;
            const int arr = g >> 10, u = g & 1023;
            const int row = u >> 3, c = u & 7;
            if (row < rows) {
                const __nv_bfloat16* src = (arr ? g_Kl : g_Kh) + ((size_t)bh*Lv + lo + row)*DKv + c*8;
                cp_async16(smb + offK0 + (arr ? KLH : 0u) + (uint32_t)(row*72 + c*8)*2, src);
            }
        }
    }
    asm volatile("cp.async.commit_group;\n" ::: "memory");

    const int wm1 = (wid >> 3) * 16;
    const int wn1 = (wid & 7) * 16;

    asm volatile("cp.async.wait_group 0;\n" ::: "memory");
    __syncthreads();                                  // Q + K0 ready

    uint32_t aHq[4][4], aLq[4][4];                    // hoisted Q fragments
#pragma unroll
    for (int ks = 0; ks < 4; ++ks) {
        const uint32_t arow = (uint32_t)(((wm1 + (lane & 15))*72 + ks*16 + ((lane >> 4) << 3)) * 2);
        LDSM_X4(aHq[ks][0], aHq[ks][1], aHq[ks][2], aHq[ks][3], smb + offQH + arow);
        LDSM_X4(aLq[ks][0], aLq[ks][1], aLq[ks][2], aLq[ks][3], smb + offQL + arow);
    }

    for (int ci = 0; ci < nch; ++ci) {
        if (ci > 0) {
            asm volatile("cp.async.wait_group 0;\n" ::: "memory");
            __syncthreads();
        }
        if (ci + 1 < nch) {
            const int kb2 = lo + (ci+1)*128;
            const int rows = min(128, hi - kb2 + 1);
            const uint32_t sb = ((ci+1) & 1) ? offK1 : offK0;
#pragma unroll
            for (int it = 0; it < 4; ++it) {
                const int g = tid + it * 512;
                const int arr = g >> 10, u = g & 1023;
                const int row = u >> 3, c = u & 7;
                if (row < rows) {
                    const __nv_bfloat16* src = (arr ? g_Kl : g_Kh) + ((size_t)bh*Lv + kb2 + row)*DKv + c*8;
                    cp_async16(smb + sb + (arr ? KLH : 0u) + (uint32_t)(row*72 + c*8)*2, src);
                }
            }
            asm volatile("cp.async.commit_group;\n" ::: "memory");
        }

        const uint32_t kst = (ci & 1) ? offK1 : offK0;
        float acc[2][4];
#pragma unroll
        for (int ni = 0; ni < 2; ++ni)
#pragma unroll
            for (int r = 0; r < 4; ++r) acc[ni][r] = 0.f;

#pragma unroll
        for (int ks = 0; ks < 4; ++ks) {
            const int kb = ks * 16;
            uint32_t bH[2][2], bL[2][2];
            const uint32_t brow = (uint32_t)((((wn1 + (lane & 7) + ((lane >> 4) << 3))*72)
                                 + kb + (((lane >> 3) & 1) << 3)) * 2);
            uint32_t r0, r1, r2, r3;
            LDSM_X4(r0, r1, r2, r3, smb + kst + brow);
            bH[0][0]=r0; bH[0][1]=r1; bH[1][0]=r2; bH[1][1]=r3;
            LDSM_X4(r0, r1, r2, r3, smb + kst + KLH + brow);
            bL[0][0]=r0; bL[0][1]=r1; bL[1][0]=r2; bL[1][1]=r3;
            mma_bf16(acc[0], aHq[ks], bH[0]);
            mma_bf16(acc[1], aHq[ks], bH[1]);
            mma_bf16(acc[0], aHq[ks], bL[0]);
            mma_bf16(acc[1], aHq[ks], bL[1]);
            mma_bf16(acc[0], aLq[ks], bH[0]);
            mma_bf16(acc[1], aLq[ks], bH[1]);
        }

        const int kbase = lo + ci * 128;
#pragma unroll
        for (int ni = 0; ni < 2; ++ni) {
#pragma unroll
            for (int half = 0; half < 2; ++half) {
                const int r = wm1 + (lane >> 2) + half * 8;
                const int q = q0 + r;
                const int cc = wn1 + ni*8 + ((lane & 3) << 1);
                const int k = kbase + cc;
                const int j = k - lo;
                if (j < W)
                    S[r*SW + j] = acc[ni][half*2+0]*0.125f - g_bias_lut[abs(q - k)];
                if (j + 1 < W)
                    S[r*SW + j + 1] = acc[ni][half*2+1]*0.125f - g_bias_lut[abs(q - k - 1)];
            }
        }
    }
    __syncthreads();

    // ---- softmax (normalize S in place) ----
    for (int rr = 0; rr < 2; ++rr) {
        const int r = wid * 2 + rr;
        const int q = q0 + r;
        float* Srow = S + r * SW;
        if (!s_masked[r]) {
            const int rlo = max(0, q - hs), rhi = min(Lv - 1, q + hs);
            const int jl = rlo - lo, jh = rhi - lo;
            float mx = -INFINITY;
            for (int j = jl + lane; j <= jh; j += 32) mx = fmaxf(mx, Srow[j]);
#pragma unroll
            for (int o = 16; o > 0; o >>= 1) mx = fmaxf(mx, __shfl_xor_sync(0xffffffffu, mx, o));
            float s = 0.f;
            for (int j = jl + lane; j <= jh; j += 32) { const float e = __expf(Srow[j] - mx); Srow[j] = e; s += e; }
#pragma unroll
            for (int o = 16; o > 0; o >>= 1) s += __shfl_xor_sync(0xffffffffu, s, o);
            const float inv = 1.f / s;
            for (int j = jl + lane; j <= jh; j += 32) Srow[j] *= inv;
        } else {
            float mx = -INFINITY;
            for (int c = lane; c < Lv; c += 32) mx = fmaxf(mx, -g_bias_lut[abs(q - c)]);
#pragma unroll
            for (int o = 16; o > 0; o >>= 1) mx = fmaxf(mx, __shfl_xor_sync(0xffffffffu, mx, o));
            float s = 0.f;
            for (int c = lane; c < Lv; c += 32) s += __expf(-g_bias_lut[abs(q - c)] - mx);
#pragma unroll
            for (int o = 16; o > 0; o >>= 1) s += __shfl_xor_sync(0xffffffffu, s, o);
            if (lane == 0) { s_mx[r] = mx; s_inv[r] = 1.f / s; }
        }
    }
    __syncthreads();

    // ---- write attention rows (full 2048 wide) + bf16 band to g_Pb ------------
    const int Wp = ((W + 7) & ~7) + 8;    // padded band width (zeros beyond W)
    for (int rr = 0; rr < 2; ++rr) {
        const int r = wid * 2 + rr;
        const int q = q0 + r;
        float* rowp = attn + ((size_t)bh * Lv + q) * Lv;
        __nv_bfloat16* prow = g_Pb + ((size_t)bh * Lv + q) * PBW;
        const float* Srow = S + r * SW;
        if (!s_masked[r]) {
            const int rlo = max(0, q - hs), rhi = min(Lv - 1, q + hs);
            for (int c4 = lane * 4; c4 < Lv; c4 += 128) {
                float4 v;
                v.x = (c4+0 >= rlo && c4+0 <= rhi) ? Srow[c4+0-lo] : 0.f;
                v.y = (c4+1 >= rlo && c4+1 <= rhi) ? Srow[c4+1-lo] : 0.f;
                v.z = (c4+2 >= rlo && c4+2 <= rhi) ? Srow[c4+2-lo] : 0.f;
                v.w = (c4+3 >= rlo && c4+3 <= rhi) ? Srow[c4+3-lo] : 0.f;
                *(float4*)(rowp + c4) = v;
            }
            const int jl = rlo - lo, jh = rhi - lo;
            for (int j2 = lane * 2; j2 < Wp; j2 += 64) {
                const float p0 = (j2   >= jl && j2   <= jh) ? Srow[j2]   : 0.f;
                const float p1 = (j2+1 >= jl && j2+1 <= jh) ? Srow[j2+1] : 0.f;
                const uint32_t pk = ((uint32_t)__bfloat16_as_ushort(__float2bfloat16_rn(p1)) << 16)
                                  |  (uint32_t)__bfloat16_as_ushort(__float2bfloat16_rn(p0));
                *(uint32_t*)&prow[j2] = pk;
            }
        } else {
            const float mx = s_mx[r], inv = s_inv[r];
            for (int c4 = lane * 4; c4 < Lv; c4 += 128) {
                float4 v;
                v.x = __expf(-g_bias_lut[abs(q - (c4+0))] - mx) * inv;
                v.y = __expf(-g_bias_lut[abs(q - (c4+1))] - mx) * inv;
                v.z = __expf(-g_bias_lut[abs(q - (c4+2))] - mx) * inv;
                v.w = __expf(-g_bias_lut[abs(q - (c4+3))] - mx) * inv;
                *(float4*)(rowp + c4) = v;
            }
            for (int j2 = lane * 2; j2 < Wp; j2 += 64)
                *(uint32_t*)&prow[j2] = 0u;
        }
    }
}

// ---------------- ctx = attn @ V via HMMA ---------------------------------------
// Fast path (tile fully unmasked): P from g_Pb via cp.async, {P,V} double-buffered.
// Slow path (any masked row): R14 fp32-read + convert, verbatim.
#define TS 72
#define STAGEB 36864u   // fast-path stage: P 18432 | Vh 9216 | Vl 9216

__global__ void __launch_bounds__(256) av2_kernel(const float* __restrict__ attn_arg,
    const float* __restrict__ mask, const int* __restrict__ ws_p)
{
    const int q0 = blockIdx.x << 7;
    const int bh = blockIdx.y;
    const int b = bh >> 4, h = bh & 15;
    const int hs = (*ws_p) >> 1;
    const int tid = threadIdx.x, wid = tid >> 5, lane = tid & 31;

    const float* attn = attn_arg ? attn_arg : g_attn_fb;

    extern __shared__ __align__(16) __nv_bfloat16 smy[];
    const uint32_t smb = smem_u32(smy);

    __shared__ int s_all;
    if (tid == 0) s_all = 1;
    __syncthreads();
    if (tid < 128 && mask[b * Lv + q0 + tid] == 0.f) s_all = 0;
    __syncthreads();
    const int allm = s_all;

    const int wm = (wid >> 1) * 32, wn = (wid & 1) * 32;
    float acc[2][4][4];
#pragma unroll
    for (int mi = 0; mi < 2; ++mi)
#pragma unroll
        for (int ni = 0; ni < 4; ++ni)
#pragma unroll
            for (int r = 0; r < 4; ++r) acc[mi][ni][r] = 0.f;

    const __nv_bfloat16* vh = g_Vth + (size_t)bh * DKv * Lv;
    const __nv_bfloat16* vl = g_Vtl + (size_t)bh * DKv * Lv;

    if (allm) {
        // ---------------- fast path: bf16 band P via cp.async ------------------
        const int a = q0 - hs;
        const int mstart = (a > 0) ? ((a >> 6) << 6) : 0;
        int e = q0 + 127 + hs; if (e > Lv - 1) e = Lv - 1;
        const int mlast = (e >> 6) << 6;
        const int nchv = ((mlast - mstart) >> 6) + 1;

        auto loadPV = [&](int m0, int st) {
            const uint32_t sb = smb + (uint32_t)st * STAGEB;
            // P: 128 rows x 64 cols bf16
#pragma unroll
            for (int it = 0; it < 4; ++it) {
                const int f = tid + it * 256;        // 0..1023
                const int row = f >> 3, c = f & 7;
                const int q = q0 + row;
                const int q0s = q & ~31;
                int lor = q0s - hs; if (lor < 0) lor = 0; lor &= ~7;
                int hir = q0s + 31 + hs; if (hir > Lv - 1) hir = Lv - 1;
                int Wr = hir - lor + 1; if (Wr > SW) Wr = SW;
                const int j = m0 + c * 8 - lor;
                const uint32_t dst = sb + (uint32_t)(row * TS + c * 8) * 2u;
                if (j >= 0 && j < Wr) {
                    cp_async16(dst, g_Pb + ((size_t)bh * Lv + q) * PBW + j);
                } else {
                    uint4 z; z.x = 0; z.y = 0; z.z = 0; z.w = 0;
                    *(uint4*)((char*)smy + (dst - smb)) = z;
                }
            }
            // V: 64 d x 64 k, hi + lo
#pragma unroll
            for (int it = 0; it < 4; ++it) {
                const int f = tid + it * 256;
                const int arr = f >> 9;
                const int u = f & 511;
                const int row = u >> 3, c = u & 7;
                const __nv_bfloat16* src = (arr ? vl : vh) + (size_t)row * Lv + m0 + c * 8;
                const uint32_t dst = sb + 18432u + (arr ? 9216u : 0u)
                                   + (uint32_t)(row * TS + c * 8) * 2u;
                cp_async16(dst, src);
            }
            asm volatile("cp.async.commit_group;\n" ::: "memory");
        };

        loadPV(mstart, 0);

        for (int ci = 0; ci < nchv; ++ci) {
            const int st = ci & 1;
            asm volatile("cp.async.wait_group 0;\n" ::: "memory");
            __syncthreads();                 // stage st ready; prior MMAs done
            if (ci + 1 < nchv) loadPV(mstart + (ci + 1) * 64, st ^ 1);

            const uint32_t sb = smb + (uint32_t)st * STAGEB;
#pragma unroll
            for (int ks = 0; ks < 4; ++ks) {
                const int kb = ks * 16;
                uint32_t aP[2][4], bVh[4][2], bVl[4][2];
                const uint32_t arow = (uint32_t)(((wm + (lane & 15)) * TS + kb + ((lane >> 4) << 3)) * 2);
#pragma unroll
                for (int mi = 0; mi < 2; ++mi) {
                    const uint32_t ad = sb + arow + (uint32_t)(mi * 16 * TS * 2);
                    LDSM_X4(aP[mi][0], aP[mi][1], aP[mi][2], aP[mi][3], ad);
                }
                const uint32_t brow = (uint32_t)((((wn + (lane & 7) + ((lane >> 4) << 3)) * TS)
                                     + kb + (((lane >> 3) & 1) << 3)) * 2);
#pragma unroll
                for (int np = 0; np < 2; ++np) {
                    const uint32_t bd = sb + 18432u + brow + (uint32_t)(np * 16 * TS * 2);
                    uint32_t r0, r1, r2, r3;
                    LDSM_X4(r0, r1, r2, r3, bd);
                    bVh[np*2][0] = r0; bVh[np*2][1] = r1; bVh[np*2+1][0] = r2; bVh[np*2+1][1] = r3;
                    LDSM_X4(r0, r1, r2, r3, bd + 9216u);
                    bVl[np*2][0] = r0; bVl[np*2][1] = r1; bVl[np*2+1][0] = r2; bVl[np*2+1][1] = r3;
                }
#pragma unroll
                for (int mi = 0; mi < 2; ++mi)
#pragma unroll
                    for (int ni = 0; ni < 4; ++ni) {
                        mma_bf16(acc[mi][ni], aP[mi], bVh[ni]);
                        mma_bf16(acc[mi][ni], aP[mi], bVl[ni]);
                    }
            }
        }
    } else {
        // ---------------- slow path: fp32 attention read + convert (R14) -------
        const uint32_t PB = 128 * TS * 2;
        const uint32_t VST = 2 * 64 * TS * 2;
        const float* abase = attn + (size_t)bh * Lv * Lv;
        const int mstart = 0, mlast = Lv - 64;
        const int nchv = ((mlast - mstart) >> 6) + 1;

        auto loadV = [&](int m0, int st) {
            const uint32_t sb = smb + PB + (uint32_t)st * VST;
#pragma unroll
            for (int it = 0; it < 4; ++it) {
                const int f = tid + it * 256;
                const int arr = f >> 9;
                const int u = f & 511;
                const int row = u >> 3, c = u & 7;
                const __nv_bfloat16* src = (arr ? vl : vh) + (size_t)row * Lv + m0 + c * 8;
                const uint32_t dst = sb + (arr ? 9216u : 0u) + (uint32_t)(row * TS + c * 8) * 2u;
                cp_async16(dst, src);
            }
            asm volatile("cp.async.commit_group;\n" ::: "memory");
        };

        loadV(mstart, 0);

        for (int ci = 0; ci < nchv; ++ci) {
            const int m0 = mstart + ci * 64;
            const int st = ci & 1;
            asm volatile("cp.async.wait_group 0;\n" ::: "memory");
            __syncthreads();

            if (ci + 1 < nchv) loadV(m0 + 64, st ^ 1);

#pragma unroll
            for (int it = 0; it < 8; ++it) {
                const int f = tid + it * 256;
                const int row = f >> 4, c4 = (f & 15) << 2;
                const float4 aa = *(const float4*)(abase + (size_t)(q0 + row) * Lv + m0 + c4);
                const uint32_t p0 = ((uint32_t)__bfloat16_as_ushort(__float2bfloat16_rn(aa.y)) << 16)
                                  |  (uint32_t)__bfloat16_as_ushort(__float2bfloat16_rn(aa.x));
                const uint32_t p1 = ((uint32_t)__bfloat16_as_ushort(__float2bfloat16_rn(aa.w)) << 16)
                                  |  (uint32_t)__bfloat16_as_ushort(__float2bfloat16_rn(aa.z));
                uint2 pv; pv.x = p0; pv.y = p1;
                *(uint2*)((char*)smy + (size_t)(row * TS + c4) * 2) = pv;
            }
            __syncthreads();

            const uint32_t vbase = smb + PB + (uint32_t)st * VST;
#pragma unroll
            for (int ks = 0; ks < 4; ++ks) {
                const int kb = ks * 16;
                uint32_t aP[2][4], bVh[4][2], bVl[4][2];
                const uint32_t arow = (uint32_t)(((wm + (lane & 15)) * TS + kb + ((lane >> 4) << 3)) * 2);
#pragma unroll
                for (int mi = 0; mi < 2; ++mi) {
                    const uint32_t ad = smb + arow + (uint32_t)(mi * 16 * TS * 2);
                    LDSM_X4(aP[mi][0], aP[mi][1], aP[mi][2], aP[mi][3], ad);
                }
                const uint32_t brow = (uint32_t)((((wn + (lane & 7) + ((lane >> 4) << 3)) * TS)
                                     + kb + (((lane >> 3) & 1) << 3)) * 2);
#pragma unroll
                for (int np = 0; np < 2; ++np) {
                    const uint32_t bd = vbase + brow + (uint32_t)(np * 16 * TS * 2);
                    uint32_t r0, r1, r2, r3;
                    LDSM_X4(r0, r1, r2, r3, bd);
                    bVh[np*2][0] = r0; bVh[np*2][1] = r1; bVh[np*2+1][0] = r2; bVh[np*2+1][1] = r3;
                    LDSM_X4(r0, r1, r2, r3, bd + 9216u);
                    bVl[np*2][0] = r0; bVl[np*2][1] = r1; bVl[np*2+1][0] = r2; bVl[np*2+1][1] = r3;
                }
#pragma unroll
                for (int mi = 0; mi < 2; ++mi)
#pragma unroll
                    for (int ni = 0; ni < 4; ++ni) {
                        mma_bf16(acc[mi][ni], aP[mi], bVh[ni]);
                        mma_bf16(acc[mi][ni], aP[mi], bVl[ni]);
                    }
            }
        }
    }

    // epilogue: write hi/lo bf16 split directly into g_Ah/g_Al (slot 0 = A of Wo GEMM)
#pragma unroll
    for (int mi = 0; mi < 2; ++mi) {
#pragma unroll
        for (int half = 0; half < 2; ++half) {
            const int q = q0 + wm + mi * 16 + (lane >> 2) + half * 8;
            const size_t rowbase = ((size_t)b * Lv + q) * DMv + h * DKv;
#pragma unroll
            for (int ni = 0; ni < 4; ++ni) {
                const int d = wn + ni * 8 + ((lane & 3) << 1);
                const float vx = acc[mi][ni][half*2+0];
                const float vy = acc[mi][ni][half*2+1];
                const __nv_bfloat16 hx = __float2bfloat16_rn(vx);
                const __nv_bfloat16 lx = __float2bfloat16_rn(vx - __bfloat162float(hx));
                const __nv_bfloat16 hy = __float2bfloat16_rn(vy);
                const __nv_bfloat16 ly = __float2bfloat16_rn(vy - __bfloat162float(hy));
                ushort2 hv; hv.x = __bfloat16_as_ushort(hx); hv.y = __bfloat16_as_ushort(hy);
                ushort2 lv; lv.x = __bfloat16_as_ushort(lx); lv.y = __bfloat16_as_ushort(ly);
                *(ushort2*)&g_Ah[rowbase + d] = hv;
                *(ushort2*)&g_Al[rowbase + d] = lv;
            }
        }
    }
}

// ---------------- residual + LayerNorm -----------------------------------------
__global__ void __launch_bounds__(256) ln_kernel(const float* __restrict__ qin,
    const float* __restrict__ lnw, const float* __restrict__ lnb,
    float* __restrict__ out)
{
    const int m = blockIdx.x;
    const int tid = threadIdx.x;
    __shared__ float xs[DMv];
    __shared__ float red[32];

    float s = 0.f;
    for (int i = tid; i < DMv; i += 256) {
        const float v = g_proj[(size_t)m * DMv + i] + qin[(size_t)m * DMv + i];
        xs[i] = v; s += v;
    }
    s = blk_reduce_sum(s, red);
    const float mean = s * (1.f / DMv);

    float vs = 0.f;
    for (int i = tid; i < DMv; i += 256) { const float d = xs[i] - mean; vs += d * d; }
    vs = blk_reduce_sum(vs, red);
    const float inv = rsqrtf(vs * (1.f / DMv) + 1e-6f);

    for (int i = tid; i < DMv; i += 256)
        out[(size_t)m * DMv + i] = (xs[i] - mean) * inv * lnw[i] + lnb[i];
}

// ---------------- launcher ------------------------------------------------------
extern "C" void kernel_launch(void* const* d_in, const int* in_sizes, int n_in,
                              void* d_out, int out_size)
{
    const float* q    = (const float*)d_in[0];
    const float* k    = (const float*)d_in[1];
    const float* v    = (const float*)d_in[2];
    const float* mask = (const float*)d_in[3];
    const float* Wq   = (const float*)d_in[4];
    const float* Wk   = (const float*)d_in[5];
    const float* Wv   = (const float*)d_in[6];
    const float* Wo   = (const float*)d_in[7];
    const float* scl  = (const float*)d_in[8];
    const float* tau  = (const float*)d_in[9];
    const float* lnw  = (const float*)d_in[10];
    const float* lnb  = (const float*)d_in[11];
    const int*   ws   = (const int*)d_in[12];
    (void)in_sizes; (void)n_in;

    const int gemm_smem = 2 * 4 * TILEB;                        // 81920 B
    const int sps_smem  = 32*SW*4 + 2*32*72*2 + 2*2*128*72*2;   // 219648 B
    const int av_smem   = 2 * STAGEB;                           // 73728 B
    cudaFuncSetAttribute(tc_gemm, cudaFuncAttributeMaxDynamicSharedMemorySize, gemm_smem);
    cudaFuncSetAttribute(sps_kernel, cudaFuncAttributeMaxDynamicSharedMemorySize, sps_smem);
    cudaFuncSetAttribute(av2_kernel, cudaFuncAttributeMaxDynamicSharedMemorySize, av_smem);

    float* xout = (float*)d_out;
    const long long XN = (long long)Bv * Lv * DMv;
    const long long AN = (long long)BHv * Lv * Lv;
    float* attn_out = ((long long)out_size >= XN + AN) ? (xout + XN) : nullptr;

    const int A4 = Mv * DMv / 4;
    const int B4 = DMv * DMv / 4;
    const dim3 gg(DMv / 128, Mv / 128);   // (8, 32)

    bias_lut_kernel<<<8, 256>>>(scl, tau);

    splitA3_kernel<<<dim3(A4/256, 1, 3), 256>>>(q, k, v);
    splitB3_kernel<<<dim3(B4/256, 1, 3), 256>>>(Wq, Wk, Wv);
    tc_gemm<<<gg, 256, gemm_smem>>>(0);
    tc_gemm<<<gg, 256, gemm_smem>>>(1);
    tc_gemm<<<gg, 256, gemm_smem>>>(2);

    sps_kernel<<<dim3(Lv/32, BHv), 512, sps_smem>>>(attn_out, mask, ws);
    av2_kernel<<<dim3(Lv/128, BHv), 256, av_smem>>>(attn_out, mask, ws);   // writes split A (slot 0)

    splitB1_kernel<<<B4/256, 256>>>(Wo);
    tc_gemm<<<gg, 256, gemm_smem>>>(3);

    ln_kernel<<<Mv, 256>>>(q, lnw, lnb, xout);
}